// round 4
// baseline (speedup 1.0000x reference)
#include <cuda_runtime.h>
#include <cuda_bf16.h>
#include <cstdint>

// ---------------- problem constants ----------------
constexpr int Bb   = 2;
constexpr int Cc   = 2048;
constexpr int Dd   = 1024;     // hidden
constexpr int Ii   = 2048;     // GLU intermediate
constexpr int TWOI = 2 * Ii;   // 4096
constexpr int Ee   = 8;        // experts
constexpr int Kk   = 2;        // top-k
constexpr int Nn   = Bb * Cc;  // 4096 tokens
constexpr int NS   = Nn * Kk;  // 8192 slots
constexpr int CAP  = 1280;     // int(N*K*1.25/E)

// ---------------- scratch (device globals; no allocs allowed) ----------------
__device__ float g_Xe[Ee * CAP * Dd];     // 40 MB  dispatched inputs
__device__ float g_H [Ee * CAP * TWOI];   // 160 MB GEMM1 output
__device__ float g_Hg[Ee * CAP * Ii];     // 80 MB  after GLU
__device__ float g_Oe[Ee * CAP * Dd];     // 40 MB  GEMM2 output
__device__ int   g_slot_e[NS];
__device__ int   g_slot_pos[NS];          // -1 if dropped
__device__ float g_slot_gate[NS];
__device__ int   g_count[Ee];

// ---------------- helpers ----------------
__device__ __forceinline__ uint32_t f2tf32(float f) {
    uint32_t r;
    asm("cvt.rna.tf32.f32 %0, %1;" : "=r"(r) : "f"(f));
    return r;
}

__device__ __forceinline__ void mma_tf32(float& c0, float& c1, float& c2, float& c3,
                                         uint32_t a0, uint32_t a1, uint32_t a2, uint32_t a3,
                                         uint32_t b0, uint32_t b1) {
    asm volatile(
        "mma.sync.aligned.m16n8k8.row.col.f32.tf32.tf32.f32 "
        "{%0,%1,%2,%3}, {%4,%5,%6,%7}, {%8,%9}, {%0,%1,%2,%3};\n"
        : "+f"(c0), "+f"(c1), "+f"(c2), "+f"(c3)
        : "r"(a0), "r"(a1), "r"(a2), "r"(a3), "r"(b0), "r"(b1));
}

// ---------------- 1) router: logits, top-2, softmax ----------------
__global__ __launch_bounds__(256) void router_kernel(const float* __restrict__ x,
                                                     const float* __restrict__ Wg) {
    int warp = threadIdx.x >> 5;
    int lane = threadIdx.x & 31;
    int token = blockIdx.x * 8 + warp;
    if (token >= Nn) return;

    const float* xr = x + (size_t)token * Dd;
    float acc[Ee];
#pragma unroll
    for (int e = 0; e < Ee; e++) acc[e] = 0.f;

    for (int k = lane; k < Dd; k += 32) {
        float xv = xr[k];
#pragma unroll
        for (int e = 0; e < Ee; e++) acc[e] += xv * Wg[e * Dd + k];
    }
#pragma unroll
    for (int e = 0; e < Ee; e++) {
#pragma unroll
        for (int off = 16; off > 0; off >>= 1)
            acc[e] += __shfl_xor_sync(0xffffffffu, acc[e], off);
    }
    if (lane == 0) {
        // top-1 (strict > => lowest index wins ties, matches lax.top_k)
        float v0 = -1e30f; int e0 = 0;
#pragma unroll
        for (int e = 0; e < Ee; e++) { if (acc[e] > v0) { v0 = acc[e]; e0 = e; } }
        float v1 = -1e30f; int e1 = 0;
#pragma unroll
        for (int e = 0; e < Ee; e++) { if (e != e0 && acc[e] > v1) { v1 = acc[e]; e1 = e; } }
        // softmax over [v0, v1], v0 >= v1
        float t  = __expf(v1 - v0);
        // use precise expf for accuracy
        t = expf(v1 - v0);
        float g0 = 1.0f / (1.0f + t);
        float g1 = t / (1.0f + t);
        int s = token * 2;
        g_slot_e[s]        = e0;
        g_slot_e[s + 1]    = e1;
        g_slot_gate[s]     = g0;
        g_slot_gate[s + 1] = g1;
    }
}

// ---------------- 2) capacity-limited assignment scan (1 block) ----------------
__global__ __launch_bounds__(1024) void scan_kernel() {
    __shared__ int cnt[1024][Ee];   // 32 KB
    int t = threadIdx.x;

    int local[Ee];
#pragma unroll
    for (int j = 0; j < Ee; j++) local[j] = 0;

    int base = t * 8;
#pragma unroll
    for (int i = 0; i < 8; i++) {
        int e = g_slot_e[base + i];
#pragma unroll
        for (int j = 0; j < Ee; j++) local[j] += (e == j);
    }
#pragma unroll
    for (int j = 0; j < Ee; j++) cnt[t][j] = local[j];
    __syncthreads();

    // inclusive Hillis-Steele scan over 1024 threads, 8-wide payload
    for (int off = 1; off < 1024; off <<= 1) {
        int v[Ee];
        if (t >= off) {
#pragma unroll
            for (int j = 0; j < Ee; j++) v[j] = cnt[t - off][j];
        }
        __syncthreads();
        if (t >= off) {
#pragma unroll
            for (int j = 0; j < Ee; j++) cnt[t][j] += v[j];
        }
        __syncthreads();
    }

    int run[Ee];
#pragma unroll
    for (int j = 0; j < Ee; j++) run[j] = cnt[t][j] - local[j];  // exclusive base

#pragma unroll
    for (int i = 0; i < 8; i++) {
        int s = base + i;
        int e = g_slot_e[s];
        int p = 0;
#pragma unroll
        for (int j = 0; j < Ee; j++) {
            if (e == j) { p = run[j]; run[j] = p + 1; }
        }
        g_slot_pos[s] = (p < CAP) ? p : -1;
    }

    if (t == 1023) {
#pragma unroll
        for (int j = 0; j < Ee; j++) {
            int c = cnt[1023][j];
            g_count[j] = (c < CAP) ? c : CAP;
        }
    }
}

// ---------------- 3) gather into dense per-expert batches ----------------
__global__ __launch_bounds__(256) void gather_kernel(const float* __restrict__ x) {
    int s = blockIdx.x;
    int p = g_slot_pos[s];
    if (p < 0) return;
    int e = g_slot_e[s];
    int token = s >> 1;
    const float4* src = (const float4*)(x + (size_t)token * Dd);
    float4* dst = (float4*)(g_Xe + ((size_t)e * CAP + p) * Dd);
    int i = threadIdx.x;                // 256 threads, Dd/4 = 256
    dst[i] = src[i];
}

// ---------------- 4) tiled tf32 grouped GEMM ----------------
// C[e] (CAP x Ncols) = A[e] (CAP x Kdim) * B[e] (Kdim x Ncols)
// grid: (Ncols/128, CAP/128, E); block: 256 threads (8 warps, 4x2)
constexpr int BM = 128, BN = 128, BK = 32;

__global__ __launch_bounds__(256) void gemm_tf32(const float* __restrict__ A,
                                                 const float* __restrict__ B,
                                                 float* __restrict__ C,
                                                 int Kdim, int Ncols) {
    int e = blockIdx.z;
    int cntm = g_count[e];
    int m0 = blockIdx.y * BM;
    if (m0 >= cntm) return;
    int n0 = blockIdx.x * BN;

    const float* Ae = A + (size_t)e * CAP * Kdim;
    const float* Be = B + (size_t)e * Kdim * Ncols;
    float*       Ce = C + (size_t)e * CAP * Ncols;

    __shared__ float As[BM][BK + 4];   // stride 36 floats (conflict-free frags)
    __shared__ float Bs[BK][BN + 8];   // stride 136 floats

    int tid  = threadIdx.x;
    int warp = tid >> 5, lane = tid & 31;
    int wm = warp & 3;      // m-warp 0..3  -> 32 rows each
    int wn = warp >> 2;     // n-warp 0..1  -> 64 cols each
    int lg = lane >> 2;     // group id 0..7
    int lt = lane & 3;      // thread-in-group 0..3

    float c[2][8][4];
#pragma unroll
    for (int mf = 0; mf < 2; mf++)
#pragma unroll
        for (int nf = 0; nf < 8; nf++)
#pragma unroll
            for (int q = 0; q < 4; q++) c[mf][nf][q] = 0.f;

    for (int k0 = 0; k0 < Kdim; k0 += BK) {
        // --- load A tile: 128 rows x 32 cols = 1024 float4 ---
#pragma unroll
        for (int r = 0; r < 4; r++) {
            int j   = tid + r * 256;
            int row = j >> 3;
            int kv  = j & 7;
            float4 v = *(const float4*)(Ae + (size_t)(m0 + row) * Kdim + k0 + kv * 4);
            As[row][kv * 4 + 0] = __uint_as_float(f2tf32(v.x));
            As[row][kv * 4 + 1] = __uint_as_float(f2tf32(v.y));
            As[row][kv * 4 + 2] = __uint_as_float(f2tf32(v.z));
            As[row][kv * 4 + 3] = __uint_as_float(f2tf32(v.w));
        }
        // --- load B tile: 32 rows x 128 cols = 1024 float4 ---
#pragma unroll
        for (int r = 0; r < 4; r++) {
            int j  = tid + r * 256;
            int kk = j >> 5;
            int nv = j & 31;
            float4 v = *(const float4*)(Be + (size_t)(k0 + kk) * Ncols + n0 + nv * 4);
            Bs[kk][nv * 4 + 0] = __uint_as_float(f2tf32(v.x));
            Bs[kk][nv * 4 + 1] = __uint_as_float(f2tf32(v.y));
            Bs[kk][nv * 4 + 2] = __uint_as_float(f2tf32(v.z));
            Bs[kk][nv * 4 + 3] = __uint_as_float(f2tf32(v.w));
        }
        __syncthreads();

#pragma unroll
        for (int ks = 0; ks < 4; ks++) {
            int kb = ks * 8;
            uint32_t a[2][4];
#pragma unroll
            for (int mf = 0; mf < 2; mf++) {
                int row = wm * 32 + mf * 16 + lg;
                int col = kb + lt;
                a[mf][0] = __float_as_uint(As[row][col]);
                a[mf][1] = __float_as_uint(As[row + 8][col]);
                a[mf][2] = __float_as_uint(As[row][col + 4]);
                a[mf][3] = __float_as_uint(As[row + 8][col + 4]);
            }
            uint32_t b[8][2];
#pragma unroll
            for (int nf = 0; nf < 8; nf++) {
                int nn = wn * 64 + nf * 8 + lg;
                b[nf][0] = __float_as_uint(Bs[kb + lt][nn]);
                b[nf][1] = __float_as_uint(Bs[kb + lt + 4][nn]);
            }
#pragma unroll
            for (int mf = 0; mf < 2; mf++)
#pragma unroll
                for (int nf = 0; nf < 8; nf++)
                    mma_tf32(c[mf][nf][0], c[mf][nf][1], c[mf][nf][2], c[mf][nf][3],
                             a[mf][0], a[mf][1], a[mf][2], a[mf][3],
                             b[nf][0], b[nf][1]);
        }
        __syncthreads();
    }

    // --- epilogue ---
#pragma unroll
    for (int mf = 0; mf < 2; mf++) {
#pragma unroll
        for (int nf = 0; nf < 8; nf++) {
            int row = m0 + wm * 32 + mf * 16 + lg;
            int col = n0 + wn * 64 + nf * 8 + lt * 2;
            Ce[(size_t)row * Ncols + col]           = c[mf][nf][0];
            Ce[(size_t)row * Ncols + col + 1]       = c[mf][nf][1];
            Ce[(size_t)(row + 8) * Ncols + col]     = c[mf][nf][2];
            Ce[(size_t)(row + 8) * Ncols + col + 1] = c[mf][nf][3];
        }
    }
}

// ---------------- 5) GLU: Hg = gelu_exact(H[:, :I]) * H[:, I:] ----------------
__global__ __launch_bounds__(256) void glu_kernel() {
    int idx = blockIdx.x * blockDim.x + threadIdx.x;   // float4 index into Hg
    constexpr int total4 = Ee * CAP * Ii / 4;
    if (idx >= total4) return;
    int row = idx / (Ii / 4);
    int iv  = idx % (Ii / 4);
    const float4 a = *(const float4*)(g_H + (size_t)row * TWOI + iv * 4);
    const float4 g = *(const float4*)(g_H + (size_t)row * TWOI + Ii + iv * 4);
    float4 o;
    o.x = 0.5f * a.x * (1.0f + erff(a.x * 0.70710678118654752f)) * g.x;
    o.y = 0.5f * a.y * (1.0f + erff(a.y * 0.70710678118654752f)) * g.y;
    o.z = 0.5f * a.z * (1.0f + erff(a.z * 0.70710678118654752f)) * g.z;
    o.w = 0.5f * a.w * (1.0f + erff(a.w * 0.70710678118654752f)) * g.w;
    *(float4*)(g_Hg + (size_t)idx * 4) = o;
}

// ---------------- 6) combine ----------------
__global__ __launch_bounds__(256) void combine_kernel(float* __restrict__ out) {
    int token = blockIdx.x;
    int s0 = token * 2, s1 = s0 + 1;
    int e0 = g_slot_e[s0], p0 = g_slot_pos[s0];
    int e1 = g_slot_e[s1], p1 = g_slot_pos[s1];
    float g0 = g_slot_gate[s0], g1 = g_slot_gate[s1];

    int i = threadIdx.x;  // 256 threads, Dd/4 = 256
    float4 acc = make_float4(0.f, 0.f, 0.f, 0.f);
    if (p0 >= 0) {
        float4 v = *(const float4*)(g_Oe + ((size_t)e0 * CAP + p0) * Dd + i * 4);
        acc.x += g0 * v.x; acc.y += g0 * v.y; acc.z += g0 * v.z; acc.w += g0 * v.w;
    }
    if (p1 >= 0) {
        float4 v = *(const float4*)(g_Oe + ((size_t)e1 * CAP + p1) * Dd + i * 4);
        acc.x += g1 * v.x; acc.y += g1 * v.y; acc.z += g1 * v.z; acc.w += g1 * v.w;
    }
    *(float4*)(out + (size_t)token * Dd + i * 4) = acc;
}

// ---------------- launch ----------------
extern "C" void kernel_launch(void* const* d_in, const int* in_sizes, int n_in,
                              void* d_out, int out_size) {
    const float* x  = (const float*)d_in[0];
    const float* Wg = (const float*)d_in[1];
    const float* W1 = (const float*)d_in[2];
    const float* W2 = (const float*)d_in[3];
    float* out = (float*)d_out;

    float *pXe, *pH, *pHg, *pOe;
    cudaGetSymbolAddress((void**)&pXe, g_Xe);
    cudaGetSymbolAddress((void**)&pH,  g_H);
    cudaGetSymbolAddress((void**)&pHg, g_Hg);
    cudaGetSymbolAddress((void**)&pOe, g_Oe);

    // 1) router
    router_kernel<<<Nn / 8, 256>>>(x, Wg);
    // 2) assignment scan
    scan_kernel<<<1, 1024>>>();
    // 3) gather
    gather_kernel<<<NS, 256>>>(x);
    // 4) GEMM1: H = Xe @ W1   (K=1024, N=4096)
    {
        dim3 grid(TWOI / BN, CAP / BM, Ee);
        gemm_tf32<<<grid, 256>>>(pXe, W1, pH, Dd, TWOI);
    }
    // 5) GLU
    {
        int total4 = Ee * CAP * Ii / 4;
        glu_kernel<<<(total4 + 255) / 256, 256>>>();
    }
    // 6) GEMM2: Oe = Hg @ W2  (K=2048, N=1024)
    {
        dim3 grid(Dd / BN, CAP / BM, Ee);
        gemm_tf32<<<grid, 256>>>(pHg, W2, pOe, Ii, Dd);
    }
    // 7) combine (fully writes output)
    combine_kernel<<<Nn, 256>>>(out);
}

// round 6
// speedup vs baseline: 1.1004x; 1.1004x over previous
#include <cuda_runtime.h>
#include <cuda_bf16.h>
#include <cstdint>

// ---------------- problem constants ----------------
constexpr int Dd   = 1024;     // hidden
constexpr int Ii   = 2048;     // GLU intermediate
constexpr int TWOI = 2 * Ii;   // 4096
constexpr int Ee   = 8;        // experts
constexpr int Nn   = 4096;     // tokens
constexpr int NS   = Nn * 2;   // slots
constexpr int CAP  = 1280;     // capacity

// ---------------- scratch ----------------
__device__ float g_Xe[Ee * CAP * Dd];     // 40 MB dispatched inputs (tf32-rounded)
__device__ float g_Hg[Ee * CAP * Ii];     // 80 MB post-GLU activations (tf32-rounded)
__device__ float g_Oe[Ee * CAP * Dd];     // 40 MB expert outputs
__device__ int   g_slot_e[NS];
__device__ int   g_slot_pos[NS];          // -1 if dropped
__device__ float g_slot_gate[NS];
__device__ int   g_count[Ee];

// ---------------- helpers ----------------
__device__ __forceinline__ uint32_t smem_u32(const void* p) {
    uint32_t a;
    asm("{ .reg .u64 t; cvta.to.shared.u64 t, %1; cvt.u32.u64 %0, t; }" : "=r"(a) : "l"(p));
    return a;
}
__device__ __forceinline__ uint32_t f2tf32(float f) {
    uint32_t r; asm("cvt.rna.tf32.f32 %0, %1;" : "=r"(r) : "f"(f)); return r;
}
__device__ __forceinline__ void cp16(uint32_t dst, const void* src) {
    asm volatile("cp.async.cg.shared.global [%0], [%1], 16;" :: "r"(dst), "l"(src));
}
#define CP_COMMIT() asm volatile("cp.async.commit_group;")
#define CP_WAIT1()  asm volatile("cp.async.wait_group 1;")
#define CP_WAIT0()  asm volatile("cp.async.wait_group 0;")

__device__ __forceinline__ void mma_tf32(float& c0, float& c1, float& c2, float& c3,
                                         uint32_t a0, uint32_t a1, uint32_t a2, uint32_t a3,
                                         uint32_t b0, uint32_t b1) {
    asm volatile(
        "mma.sync.aligned.m16n8k8.row.col.f32.tf32.tf32.f32 "
        "{%0,%1,%2,%3}, {%4,%5,%6,%7}, {%8,%9}, {%0,%1,%2,%3};\n"
        : "+f"(c0), "+f"(c1), "+f"(c2), "+f"(c3)
        : "r"(a0), "r"(a1), "r"(a2), "r"(a3), "r"(b0), "r"(b1));
}

// ---------------- smem layout constants ----------------
constexpr int AS_STRIDE = 36;                 // floats per A row (pad 4)
constexpr int BS_STRIDE = 136;                // floats per B row (pad 8)
constexpr int A_STAGE = 128 * AS_STRIDE * 4;  // 18432 B
constexpr int B_STAGE = 32 * BS_STRIDE * 4;   // 17408 B
// GEMM1 fused: A[3] | Bi[3] | Bg[3]
constexpr int G1_OFF_BI = 3 * A_STAGE;                 // 55296
constexpr int G1_OFF_BG = G1_OFF_BI + 3 * B_STAGE;     // 107520
constexpr int G1_SMEM   = G1_OFF_BG + 3 * B_STAGE;     // 159744
// GEMM2: A[3] | B[3]
constexpr int G2_OFF_B  = 3 * A_STAGE;
constexpr int G2_SMEM   = G2_OFF_B + 3 * B_STAGE;      // 107520

// ---------------- 1) router ----------------
__global__ __launch_bounds__(256) void router_kernel(const float* __restrict__ x,
                                                     const float* __restrict__ Wg) {
    int warp = threadIdx.x >> 5, lane = threadIdx.x & 31;
    int token = blockIdx.x * 8 + warp;
    if (token >= Nn) return;
    const float* xr = x + (size_t)token * Dd;
    float acc[Ee];
#pragma unroll
    for (int e = 0; e < Ee; e++) acc[e] = 0.f;
    for (int k = lane; k < Dd; k += 32) {
        float xv = xr[k];
#pragma unroll
        for (int e = 0; e < Ee; e++) acc[e] += xv * Wg[e * Dd + k];
    }
#pragma unroll
    for (int e = 0; e < Ee; e++)
#pragma unroll
        for (int off = 16; off > 0; off >>= 1)
            acc[e] += __shfl_xor_sync(0xffffffffu, acc[e], off);
    if (lane == 0) {
        float v0 = -1e30f; int e0 = 0;
#pragma unroll
        for (int e = 0; e < Ee; e++) if (acc[e] > v0) { v0 = acc[e]; e0 = e; }
        float v1 = -1e30f; int e1 = 0;
#pragma unroll
        for (int e = 0; e < Ee; e++) if (e != e0 && acc[e] > v1) { v1 = acc[e]; e1 = e; }
        float t = expf(v1 - v0);
        int s = token * 2;
        g_slot_e[s] = e0; g_slot_e[s + 1] = e1;
        g_slot_gate[s]     = 1.0f / (1.0f + t);
        g_slot_gate[s + 1] = t / (1.0f + t);
    }
}

// ---------------- 2) capacity scan ----------------
__global__ __launch_bounds__(1024) void scan_kernel() {
    __shared__ int cnt[1024][Ee];
    int t = threadIdx.x;
    int local[Ee];
#pragma unroll
    for (int j = 0; j < Ee; j++) local[j] = 0;
    int base = t * 8;
#pragma unroll
    for (int i = 0; i < 8; i++) {
        int e = g_slot_e[base + i];
#pragma unroll
        for (int j = 0; j < Ee; j++) local[j] += (e == j);
    }
#pragma unroll
    for (int j = 0; j < Ee; j++) cnt[t][j] = local[j];
    __syncthreads();
    for (int off = 1; off < 1024; off <<= 1) {
        int v[Ee];
        if (t >= off)
#pragma unroll
            for (int j = 0; j < Ee; j++) v[j] = cnt[t - off][j];
        __syncthreads();
        if (t >= off)
#pragma unroll
            for (int j = 0; j < Ee; j++) cnt[t][j] += v[j];
        __syncthreads();
    }
    int run[Ee];
#pragma unroll
    for (int j = 0; j < Ee; j++) run[j] = cnt[t][j] - local[j];
#pragma unroll
    for (int i = 0; i < 8; i++) {
        int s = base + i;
        int e = g_slot_e[s];
        int p = 0;
#pragma unroll
        for (int j = 0; j < Ee; j++)
            if (e == j) { p = run[j]; run[j] = p + 1; }
        g_slot_pos[s] = (p < CAP) ? p : -1;
    }
    if (t == 1023)
#pragma unroll
        for (int j = 0; j < Ee; j++) {
            int c = cnt[1023][j];
            g_count[j] = (c < CAP) ? c : CAP;
        }
}

// ---------------- 3) gather (pre-round to tf32) ----------------
__global__ __launch_bounds__(256) void gather_kernel(const float* __restrict__ x) {
    int s = blockIdx.x;
    int p = g_slot_pos[s];
    if (p < 0) return;
    int e = g_slot_e[s];
    int token = s >> 1;
    const float4* src = (const float4*)(x + (size_t)token * Dd);
    float4* dst = (float4*)(g_Xe + ((size_t)e * CAP + p) * Dd);
    float4 v = src[threadIdx.x];
    v.x = __uint_as_float(f2tf32(v.x));
    v.y = __uint_as_float(f2tf32(v.y));
    v.z = __uint_as_float(f2tf32(v.z));
    v.w = __uint_as_float(f2tf32(v.w));
    dst[threadIdx.x] = v;
}

// ---------------- 4) GEMM1 + fused GLU ----------------
// Per block: 128 M-rows x (128 inp cols + 128 gate cols), K = 1024, BK = 32.
// 3-stage cp.async pipeline, 1 __syncthreads per K-iter.
// grid (Ii/128=16, CAP/128=10, Ee), 256 threads.
__global__ __launch_bounds__(256, 1) void gemm1_glu_kernel(const float* __restrict__ W1) {
    extern __shared__ __align__(16) char smem[];
    constexpr int NIT = Dd / 32;   // 32
    int e = blockIdx.z;
    int m0 = blockIdx.y * 128;
    if (m0 >= g_count[e]) return;
    int n0 = blockIdx.x * 128;

    int tid = threadIdx.x;
    int warp = tid >> 5, lane = tid & 31;
    int wm = warp & 3, wn = warp >> 2;
    int lg = lane >> 2, lt = lane & 3;

    const float* Ae = g_Xe + ((size_t)e * CAP + m0) * Dd;
    const float* Be = W1 + (size_t)e * Dd * TWOI;
    uint32_t sb = smem_u32(smem);

    float ci[2][8][4], cg[2][8][4];
#pragma unroll
    for (int mf = 0; mf < 2; mf++)
#pragma unroll
        for (int nf = 0; nf < 8; nf++)
#pragma unroll
            for (int q = 0; q < 4; q++) { ci[mf][nf][q] = 0.f; cg[mf][nf][q] = 0.f; }

    int ar = tid >> 3, akv = tid & 7;    // A-load coords
    int bk = tid >> 5, bnv = tid & 31;   // B-load coords

    auto load_stage = [&](int s, int it) {
        int k0 = it * 32;
        uint32_t da = sb + s * A_STAGE;
#pragma unroll
        for (int r = 0; r < 4; r++) {
            int row = ar + r * 32;
            cp16(da + (uint32_t)(row * AS_STRIDE + akv * 4) * 4,
                 Ae + (size_t)row * Dd + k0 + akv * 4);
        }
        uint32_t dbi = sb + G1_OFF_BI + s * B_STAGE;
        uint32_t dbg = sb + G1_OFF_BG + s * B_STAGE;
#pragma unroll
        for (int r = 0; r < 4; r++) {
            int kk = bk + r * 8;
            const float* srow = Be + (size_t)(k0 + kk) * TWOI + bnv * 4;
            uint32_t off = (uint32_t)(kk * BS_STRIDE + bnv * 4) * 4;
            cp16(dbi + off, srow + n0);
            cp16(dbg + off, srow + n0 + Ii);
        }
        CP_COMMIT();
    };

    auto compute_stage = [&](int s) {
        const float* As = (const float*)(smem + s * A_STAGE);
        const float* Bi = (const float*)(smem + G1_OFF_BI + s * B_STAGE);
        const float* Bg = (const float*)(smem + G1_OFF_BG + s * B_STAGE);
#pragma unroll
        for (int ks = 0; ks < 4; ks++) {
            int kb = ks * 8;
            uint32_t a[2][4];
#pragma unroll
            for (int mf = 0; mf < 2; mf++) {
                int row = wm * 32 + mf * 16 + lg;
                a[mf][0] = __float_as_uint(As[row * AS_STRIDE + kb + lt]);
                a[mf][1] = __float_as_uint(As[(row + 8) * AS_STRIDE + kb + lt]);
                a[mf][2] = __float_as_uint(As[row * AS_STRIDE + kb + lt + 4]);
                a[mf][3] = __float_as_uint(As[(row + 8) * AS_STRIDE + kb + lt + 4]);
            }
#pragma unroll
            for (int nf = 0; nf < 8; nf++) {
                int nn = wn * 64 + nf * 8 + lg;
                uint32_t b0 = f2tf32(Bi[(kb + lt) * BS_STRIDE + nn]);
                uint32_t b1 = f2tf32(Bi[(kb + lt + 4) * BS_STRIDE + nn]);
#pragma unroll
                for (int mf = 0; mf < 2; mf++)
                    mma_tf32(ci[mf][nf][0], ci[mf][nf][1], ci[mf][nf][2], ci[mf][nf][3],
                             a[mf][0], a[mf][1], a[mf][2], a[mf][3], b0, b1);
                uint32_t h0 = f2tf32(Bg[(kb + lt) * BS_STRIDE + nn]);
                uint32_t h1 = f2tf32(Bg[(kb + lt + 4) * BS_STRIDE + nn]);
#pragma unroll
                for (int mf = 0; mf < 2; mf++)
                    mma_tf32(cg[mf][nf][0], cg[mf][nf][1], cg[mf][nf][2], cg[mf][nf][3],
                             a[mf][0], a[mf][1], a[mf][2], a[mf][3], h0, h1);
            }
        }
    };

    load_stage(0, 0);
    load_stage(1, 1);
    for (int it = 0; it < NIT; it++) {
        int s = it % 3;
        if (it < NIT - 1) { CP_WAIT1(); } else { CP_WAIT0(); }
        __syncthreads();
        if (it + 2 < NIT) load_stage((it + 2) % 3, it + 2);
        compute_stage(s);
    }

    // fused GLU epilogue: Hg = gelu_exact(inp) * gate, tf32-rounded
    float* Hge = g_Hg + (size_t)e * CAP * Ii;
#pragma unroll
    for (int mf = 0; mf < 2; mf++) {
#pragma unroll
        for (int nf = 0; nf < 8; nf++) {
            int row = m0 + wm * 32 + mf * 16 + lg;
            int col = n0 + wn * 64 + nf * 8 + lt * 2;
            float h00 = 0.5f * ci[mf][nf][0] * (1.0f + erff(ci[mf][nf][0] * 0.70710678118654752f)) * cg[mf][nf][0];
            float h01 = 0.5f * ci[mf][nf][1] * (1.0f + erff(ci[mf][nf][1] * 0.70710678118654752f)) * cg[mf][nf][1];
            float h10 = 0.5f * ci[mf][nf][2] * (1.0f + erff(ci[mf][nf][2] * 0.70710678118654752f)) * cg[mf][nf][2];
            float h11 = 0.5f * ci[mf][nf][3] * (1.0f + erff(ci[mf][nf][3] * 0.70710678118654752f)) * cg[mf][nf][3];
            *(float2*)(Hge + (size_t)row * Ii + col) =
                make_float2(__uint_as_float(f2tf32(h00)), __uint_as_float(f2tf32(h01)));
            *(float2*)(Hge + (size_t)(row + 8) * Ii + col) =
                make_float2(__uint_as_float(f2tf32(h10)), __uint_as_float(f2tf32(h11)));
        }
    }
}

// ---------------- 5) GEMM2: Oe = Hg @ W2 ----------------
// 128x128 tile, K = 2048, BK = 32, 3-stage cp.async, 2 CTAs/SM.
// grid (Dd/128=8, CAP/128=10, Ee), 256 threads.
__global__ __launch_bounds__(256, 2) void gemm2_kernel(const float* __restrict__ W2) {
    extern __shared__ __align__(16) char smem[];
    constexpr int NIT = Ii / 32;   // 64
    int e = blockIdx.z;
    int m0 = blockIdx.y * 128;
    if (m0 >= g_count[e]) return;
    int n0 = blockIdx.x * 128;

    int tid = threadIdx.x;
    int warp = tid >> 5, lane = tid & 31;
    int wm = warp & 3, wn = warp >> 2;
    int lg = lane >> 2, lt = lane & 3;

    const float* Ae = g_Hg + ((size_t)e * CAP + m0) * Ii;
    const float* Be = W2 + (size_t)e * Ii * Dd;
    uint32_t sb = smem_u32(smem);

    float c[2][8][4];
#pragma unroll
    for (int mf = 0; mf < 2; mf++)
#pragma unroll
        for (int nf = 0; nf < 8; nf++)
#pragma unroll
            for (int q = 0; q < 4; q++) c[mf][nf][q] = 0.f;

    int ar = tid >> 3, akv = tid & 7;
    int bk = tid >> 5, bnv = tid & 31;

    auto load_stage = [&](int s, int it) {
        int k0 = it * 32;
        uint32_t da = sb + s * A_STAGE;
#pragma unroll
        for (int r = 0; r < 4; r++) {
            int row = ar + r * 32;
            cp16(da + (uint32_t)(row * AS_STRIDE + akv * 4) * 4,
                 Ae + (size_t)row * Ii + k0 + akv * 4);
        }
        uint32_t db = sb + G2_OFF_B + s * B_STAGE;
#pragma unroll
        for (int r = 0; r < 4; r++) {
            int kk = bk + r * 8;
            cp16(db + (uint32_t)(kk * BS_STRIDE + bnv * 4) * 4,
                 Be + (size_t)(k0 + kk) * Dd + n0 + bnv * 4);
        }
        CP_COMMIT();
    };

    auto compute_stage = [&](int s) {
        const float* As = (const float*)(smem + s * A_STAGE);
        const float* Bs = (const float*)(smem + G2_OFF_B + s * B_STAGE);
#pragma unroll
        for (int ks = 0; ks < 4; ks++) {
            int kb = ks * 8;
            uint32_t a[2][4];
#pragma unroll
            for (int mf = 0; mf < 2; mf++) {
                int row = wm * 32 + mf * 16 + lg;
                a[mf][0] = __float_as_uint(As[row * AS_STRIDE + kb + lt]);
                a[mf][1] = __float_as_uint(As[(row + 8) * AS_STRIDE + kb + lt]);
                a[mf][2] = __float_as_uint(As[row * AS_STRIDE + kb + lt + 4]);
                a[mf][3] = __float_as_uint(As[(row + 8) * AS_STRIDE + kb + lt + 4]);
            }
#pragma unroll
            for (int nf = 0; nf < 8; nf++) {
                int nn = wn * 64 + nf * 8 + lg;
                uint32_t b0 = f2tf32(Bs[(kb + lt) * BS_STRIDE + nn]);
                uint32_t b1 = f2tf32(Bs[(kb + lt + 4) * BS_STRIDE + nn]);
#pragma unroll
                for (int mf = 0; mf < 2; mf++)
                    mma_tf32(c[mf][nf][0], c[mf][nf][1], c[mf][nf][2], c[mf][nf][3],
                             a[mf][0], a[mf][1], a[mf][2], a[mf][3], b0, b1);
            }
        }
    };

    load_stage(0, 0);
    load_stage(1, 1);
    for (int it = 0; it < NIT; it++) {
        int s = it % 3;
        if (it < NIT - 1) { CP_WAIT1(); } else { CP_WAIT0(); }
        __syncthreads();
        if (it + 2 < NIT) load_stage((it + 2) % 3, it + 2);
        compute_stage(s);
    }

    float* Oe = g_Oe + (size_t)e * CAP * Dd;
#pragma unroll
    for (int mf = 0; mf < 2; mf++) {
#pragma unroll
        for (int nf = 0; nf < 8; nf++) {
            int row = m0 + wm * 32 + mf * 16 + lg;
            int col = n0 + wn * 64 + nf * 8 + lt * 2;
            *(float2*)(Oe + (size_t)row * Dd + col)       = make_float2(c[mf][nf][0], c[mf][nf][1]);
            *(float2*)(Oe + (size_t)(row + 8) * Dd + col) = make_float2(c[mf][nf][2], c[mf][nf][3]);
        }
    }
}

// ---------------- 6) combine ----------------
__global__ __launch_bounds__(256) void combine_kernel(float* __restrict__ out) {
    int token = blockIdx.x;
    int s0 = token * 2, s1 = s0 + 1;
    int e0 = g_slot_e[s0], p0 = g_slot_pos[s0];
    int e1 = g_slot_e[s1], p1 = g_slot_pos[s1];
    float g0 = g_slot_gate[s0], g1 = g_slot_gate[s1];
    int i = threadIdx.x;
    float4 acc = make_float4(0.f, 0.f, 0.f, 0.f);
    if (p0 >= 0) {
        float4 v = *(const float4*)(g_Oe + ((size_t)e0 * CAP + p0) * Dd + i * 4);
        acc.x += g0 * v.x; acc.y += g0 * v.y; acc.z += g0 * v.z; acc.w += g0 * v.w;
    }
    if (p1 >= 0) {
        float4 v = *(const float4*)(g_Oe + ((size_t)e1 * CAP + p1) * Dd + i * 4);
        acc.x += g1 * v.x; acc.y += g1 * v.y; acc.z += g1 * v.z; acc.w += g1 * v.w;
    }
    *(float4*)(out + (size_t)token * Dd + i * 4) = acc;
}

// ---------------- launch ----------------
extern "C" void kernel_launch(void* const* d_in, const int* in_sizes, int n_in,
                              void* d_out, int out_size) {
    const float* x  = (const float*)d_in[0];
    const float* Wg = (const float*)d_in[1];
    const float* W1 = (const float*)d_in[2];
    const float* W2 = (const float*)d_in[3];
    float* out = (float*)d_out;

    cudaFuncSetAttribute(gemm1_glu_kernel,
                         cudaFuncAttributeMaxDynamicSharedMemorySize, G1_SMEM);
    cudaFuncSetAttribute(gemm2_kernel,
                         cudaFuncAttributeMaxDynamicSharedMemorySize, G2_SMEM);

    router_kernel<<<Nn / 8, 256>>>(x, Wg);
    scan_kernel<<<1, 1024>>>();
    gather_kernel<<<NS, 256>>>(x);
    gemm1_glu_kernel<<<dim3(Ii / 128, CAP / 128, Ee), 256, G1_SMEM>>>(W1);
    gemm2_kernel   <<<dim3(Dd / 128, CAP / 128, Ee), 256, G2_SMEM>>>(W2);
    combine_kernel<<<Nn, 256>>>(out);
}

// round 8
// speedup vs baseline: 1.7781x; 1.6158x over previous
#include <cuda_runtime.h>
#include <cuda_fp16.h>
#include <cstdint>

// ---------------- problem constants ----------------
constexpr int Dd   = 1024;     // hidden
constexpr int Ii   = 2048;     // GLU intermediate
constexpr int TWOI = 2 * Ii;   // 4096
constexpr int Ee   = 8;        // experts
constexpr int Nn   = 4096;     // tokens
constexpr int NS   = Nn * 2;   // slots
constexpr int CAP  = 1280;     // capacity

// ---------------- scratch ----------------
__device__ __half g_Xe[(size_t)Ee * CAP * Dd];    // 20 MB  dispatched inputs (fp16)
__device__ __half g_Hg[(size_t)Ee * CAP * Ii];    // 42 MB  post-GLU activations (fp16)
__device__ float  g_Oe[(size_t)Ee * CAP * Dd];    // 40 MB  expert outputs (fp32)
__device__ __half g_W1h[(size_t)Ee * Dd * TWOI];  // 64 MB  W1 fp16
__device__ __half g_W2h[(size_t)Ee * Ii * Dd];    // 32 MB  W2 fp16
__device__ int    g_slot_e[NS];
__device__ int    g_slot_pos[NS];                 // -1 if dropped
__device__ float  g_slot_gate[NS];
__device__ int    g_count[Ee];

// ---------------- helpers ----------------
__device__ __forceinline__ uint32_t smem_u32(const void* p) {
    uint32_t a;
    asm("{ .reg .u64 t; cvta.to.shared.u64 t, %1; cvt.u32.u64 %0, t; }" : "=r"(a) : "l"(p));
    return a;
}
__device__ __forceinline__ void cp16(uint32_t dst, const void* src) {
    asm volatile("cp.async.cg.shared.global [%0], [%1], 16;" :: "r"(dst), "l"(src));
}
#define CP_COMMIT() asm volatile("cp.async.commit_group;")
#define CP_WAIT1()  asm volatile("cp.async.wait_group 1;")
#define CP_WAIT0()  asm volatile("cp.async.wait_group 0;")

__device__ __forceinline__ void ldsm_x4(uint32_t& r0, uint32_t& r1, uint32_t& r2, uint32_t& r3,
                                        uint32_t addr) {
    asm volatile("ldmatrix.sync.aligned.m8n8.x4.shared.b16 {%0,%1,%2,%3}, [%4];"
        : "=r"(r0), "=r"(r1), "=r"(r2), "=r"(r3) : "r"(addr));
}
__device__ __forceinline__ void ldsm_x4_t(uint32_t& r0, uint32_t& r1, uint32_t& r2, uint32_t& r3,
                                          uint32_t addr) {
    asm volatile("ldmatrix.sync.aligned.m8n8.x4.trans.shared.b16 {%0,%1,%2,%3}, [%4];"
        : "=r"(r0), "=r"(r1), "=r"(r2), "=r"(r3) : "r"(addr));
}
__device__ __forceinline__ void mma_f16(float& c0, float& c1, float& c2, float& c3,
                                        uint32_t a0, uint32_t a1, uint32_t a2, uint32_t a3,
                                        uint32_t b0, uint32_t b1) {
    asm volatile(
        "mma.sync.aligned.m16n8k16.row.col.f32.f16.f16.f32 "
        "{%0,%1,%2,%3}, {%4,%5,%6,%7}, {%8,%9}, {%0,%1,%2,%3};\n"
        : "+f"(c0), "+f"(c1), "+f"(c2), "+f"(c3)
        : "r"(a0), "r"(a1), "r"(a2), "r"(a3), "r"(b0), "r"(b1));
}
__device__ __forceinline__ float gelu(float a) {
    return 0.5f * a * (1.0f + erff(a * 0.70710678118654752f));
}
__device__ __forceinline__ uint32_t packh2(float lo, float hi) {
    __half2 h = __floats2half2_rn(lo, hi);
    return *reinterpret_cast<uint32_t*>(&h);
}

// ---------------- smem layout (shared by both GEMMs) ----------------
// A tile: 128 rows x 32 k halves (64B data), pitch 80B -> conflict-free ldmatrix
// B tile: 32 k-rows x 256 n halves (512B data), pitch 528B -> conflict-free ldmatrix
constexpr int A_PITCH = 80;
constexpr int B_PITCH = 528;
constexpr int A_ST = 128 * A_PITCH;            // 10240
constexpr int B_ST = 32 * B_PITCH;             // 16896
constexpr int SM_B_OFF = 3 * A_ST;             // 30720
constexpr int SMEM_TOT = SM_B_OFF + 3 * B_ST;  // 81408

// ---------------- 0) fp32 -> fp16 weight prepass ----------------
__global__ __launch_bounds__(256) void to_half_kernel(const float4* __restrict__ src,
                                                      uint4* __restrict__ dst, int n8) {
    int i = blockIdx.x * 256 + threadIdx.x;
    if (i >= n8) return;
    float4 a = src[2 * i], b = src[2 * i + 1];
    uint4 o;
    o.x = packh2(a.x, a.y);
    o.y = packh2(a.z, a.w);
    o.z = packh2(b.x, b.y);
    o.w = packh2(b.z, b.w);
    dst[i] = o;
}

// ---------------- 1) router ----------------
__global__ __launch_bounds__(256) void router_kernel(const float* __restrict__ x,
                                                     const float* __restrict__ Wg) {
    int warp = threadIdx.x >> 5, lane = threadIdx.x & 31;
    int token = blockIdx.x * 8 + warp;
    if (token >= Nn) return;
    const float* xr = x + (size_t)token * Dd;
    float acc[Ee];
#pragma unroll
    for (int e = 0; e < Ee; e++) acc[e] = 0.f;
    for (int k = lane; k < Dd; k += 32) {
        float xv = xr[k];
#pragma unroll
        for (int e = 0; e < Ee; e++) acc[e] += xv * Wg[e * Dd + k];
    }
#pragma unroll
    for (int e = 0; e < Ee; e++)
#pragma unroll
        for (int off = 16; off > 0; off >>= 1)
            acc[e] += __shfl_xor_sync(0xffffffffu, acc[e], off);
    if (lane == 0) {
        float v0 = -1e30f; int e0 = 0;
#pragma unroll
        for (int e = 0; e < Ee; e++) if (acc[e] > v0) { v0 = acc[e]; e0 = e; }
        float v1 = -1e30f; int e1 = 0;
#pragma unroll
        for (int e = 0; e < Ee; e++) if (e != e0 && acc[e] > v1) { v1 = acc[e]; e1 = e; }
        float t = expf(v1 - v0);
        int s = token * 2;
        g_slot_e[s] = e0; g_slot_e[s + 1] = e1;
        g_slot_gate[s]     = 1.0f / (1.0f + t);
        g_slot_gate[s + 1] = t / (1.0f + t);
    }
}

// ---------------- 2) capacity scan ----------------
__global__ __launch_bounds__(1024) void scan_kernel() {
    __shared__ int cnt[1024][Ee];
    int t = threadIdx.x;
    int local[Ee];
#pragma unroll
    for (int j = 0; j < Ee; j++) local[j] = 0;
    int base = t * 8;
#pragma unroll
    for (int i = 0; i < 8; i++) {
        int e = g_slot_e[base + i];
#pragma unroll
        for (int j = 0; j < Ee; j++) local[j] += (e == j);
    }
#pragma unroll
    for (int j = 0; j < Ee; j++) cnt[t][j] = local[j];
    __syncthreads();
    for (int off = 1; off < 1024; off <<= 1) {
        int v[Ee];
        if (t >= off)
#pragma unroll
            for (int j = 0; j < Ee; j++) v[j] = cnt[t - off][j];
        __syncthreads();
        if (t >= off)
#pragma unroll
            for (int j = 0; j < Ee; j++) cnt[t][j] += v[j];
        __syncthreads();
    }
    int run[Ee];
#pragma unroll
    for (int j = 0; j < Ee; j++) run[j] = cnt[t][j] - local[j];
#pragma unroll
    for (int i = 0; i < 8; i++) {
        int s = base + i;
        int e = g_slot_e[s];
        int p = 0;
#pragma unroll
        for (int j = 0; j < Ee; j++)
            if (e == j) { p = run[j]; run[j] = p + 1; }
        g_slot_pos[s] = (p < CAP) ? p : -1;
    }
    if (t == 1023)
#pragma unroll
        for (int j = 0; j < Ee; j++) {
            int c = cnt[1023][j];
            g_count[j] = (c < CAP) ? c : CAP;
        }
}

// ---------------- 3) gather -> fp16 ----------------
__global__ __launch_bounds__(256) void gather_kernel(const float* __restrict__ x) {
    int s = blockIdx.x;
    int p = g_slot_pos[s];
    if (p < 0) return;
    int e = g_slot_e[s];
    int token = s >> 1;
    float4 v = ((const float4*)(x + (size_t)token * Dd))[threadIdx.x];
    uint2 u;
    u.x = packh2(v.x, v.y);
    u.y = packh2(v.z, v.w);
    *(uint2*)(g_Xe + ((size_t)e * CAP + p) * Dd + threadIdx.x * 4) = u;
}

// ---------------- 4) GEMM1 (fp16 mma, warp tile 64x64) + fused GLU ----------------
// Block: 128 rows x 256 cols (128 inp + 128 gate at matching n), K = 1024, BK = 32.
// 8 warps (2m x 4n); each warp: 64 rows x (32 inp + 32 gate cols) -> local GLU pairing.
// grid (Ii/128 = 16, CAP/128 = 10, Ee), 256 threads.
__global__ __launch_bounds__(256, 1) void gemm1_glu_kernel() {
    extern __shared__ __align__(16) char smem[];
    constexpr int NIT = Dd / 32;   // 32
    int e = blockIdx.z;
    int m0 = blockIdx.y * 128;
    if (m0 >= g_count[e]) return;
    int n0 = blockIdx.x * 128;

    int tid = threadIdx.x;
    int warp = tid >> 5, lane = tid & 31;
    int wm = warp & 1, wn = warp >> 1;        // 2m x 4n
    int lg = lane >> 2, lt = lane & 3;
    int r8 = lane & 7, grp = lane >> 3;

    const __half* Ae  = g_Xe + ((size_t)e * CAP + m0) * Dd;
    const __half* W1e = g_W1h + (size_t)e * Dd * TWOI;
    uint32_t sb = smem_u32(smem);

    float c[4][8][4];
#pragma unroll
    for (int mf = 0; mf < 4; mf++)
#pragma unroll
        for (int nf = 0; nf < 8; nf++)
#pragma unroll
            for (int q = 0; q < 4; q++) c[mf][nf][q] = 0.f;

    auto load_stage = [&](int s, int it) {
        int k0 = it * 32;
        uint32_t da = sb + s * A_ST;
#pragma unroll
        for (int q = 0; q < 2; q++) {
            int j = tid + q * 256;
            int row = j >> 2, seg = j & 3;
            cp16(da + (uint32_t)(row * A_PITCH + seg * 16),
                 Ae + (size_t)row * Dd + k0 + seg * 8);
        }
        uint32_t db = sb + SM_B_OFF + s * B_ST;
#pragma unroll
        for (int q = 0; q < 4; q++) {
            int j = tid + q * 256;
            int r = j >> 5, cc = j & 31;
            const __half* src = W1e + (size_t)(k0 + r) * TWOI + n0
                              + (cc & 15) * 8 + ((cc >> 4) ? Ii : 0);
            cp16(db + (uint32_t)(r * B_PITCH + cc * 16), src);
        }
        CP_COMMIT();
    };

    auto compute_stage = [&](int s) {
        uint32_t sa = sb + s * A_ST;
        uint32_t sbB = sb + SM_B_OFF + s * B_ST;
#pragma unroll
        for (int ks = 0; ks < 2; ks++) {
            uint32_t a[4][4];
#pragma unroll
            for (int mf = 0; mf < 4; mf++) {
                uint32_t addr = sa
                    + (uint32_t)((wm * 64 + mf * 16 + (grp & 1) * 8 + r8) * A_PITCH
                                 + ks * 32 + (grp >> 1) * 16);
                ldsm_x4(a[mf][0], a[mf][1], a[mf][2], a[mf][3], addr);
            }
#pragma unroll
            for (int ch = 0; ch < 4; ch++) {
                uint32_t b0, b1, b2, b3;
                uint32_t addr = sbB
                    + (uint32_t)((ks * 16 + (grp & 1) * 8 + r8) * B_PITCH
                                 + (ch >> 1) * 256 + wn * 64 + (ch & 1) * 32 + (grp >> 1) * 16);
                ldsm_x4_t(b0, b1, b2, b3, addr);
                int nf0 = ch * 2, nf1 = ch * 2 + 1;
#pragma unroll
                for (int mf = 0; mf < 4; mf++) {
                    mma_f16(c[mf][nf0][0], c[mf][nf0][1], c[mf][nf0][2], c[mf][nf0][3],
                            a[mf][0], a[mf][1], a[mf][2], a[mf][3], b0, b1);
                    mma_f16(c[mf][nf1][0], c[mf][nf1][1], c[mf][nf1][2], c[mf][nf1][3],
                            a[mf][0], a[mf][1], a[mf][2], a[mf][3], b2, b3);
                }
            }
        }
    };

    load_stage(0, 0);
    load_stage(1, 1);
    for (int it = 0; it < NIT; it++) {
        int s = it % 3;
        if (it < NIT - 1) { CP_WAIT1(); } else { CP_WAIT0(); }
        __syncthreads();
        if (it + 2 < NIT) load_stage((it + 2) % 3, it + 2);
        compute_stage(s);
    }

    // fused GLU epilogue: nf 0..3 = inp, nf+4 = gate at matching cols
#pragma unroll
    for (int mf = 0; mf < 4; mf++) {
#pragma unroll
        for (int nf = 0; nf < 4; nf++) {
            int row0 = m0 + wm * 64 + mf * 16 + lg;
            int col  = n0 + wn * 32 + nf * 8 + lt * 2;
            float* i4 = c[mf][nf];
            float* g4 = c[mf][nf + 4];
            uint32_t h01 = packh2(gelu(i4[0]) * g4[0], gelu(i4[1]) * g4[1]);
            uint32_t h23 = packh2(gelu(i4[2]) * g4[2], gelu(i4[3]) * g4[3]);
            *(uint32_t*)(g_Hg + ((size_t)e * CAP + row0) * Ii + col)       = h01;
            *(uint32_t*)(g_Hg + ((size_t)e * CAP + row0 + 8) * Ii + col)  = h23;
        }
    }
}

// ---------------- 5) GEMM2: Oe = Hg @ W2 (fp16 mma, warp tile 64x64) ----------------
// Block 128 x 256, K = 2048, BK = 32. grid (Dd/256 = 4, 10, Ee), 256 threads.
__global__ __launch_bounds__(256, 1) void gemm2_kernel() {
    extern __shared__ __align__(16) char smem[];
    constexpr int NIT = Ii / 32;   // 64
    int e = blockIdx.z;
    int m0 = blockIdx.y * 128;
    if (m0 >= g_count[e]) return;
    int n0 = blockIdx.x * 256;

    int tid = threadIdx.x;
    int warp = tid >> 5, lane = tid & 31;
    int wm = warp & 1, wn = warp >> 1;
    int lg = lane >> 2, lt = lane & 3;
    int r8 = lane & 7, grp = lane >> 3;

    const __half* Ae  = g_Hg + ((size_t)e * CAP + m0) * Ii;
    const __half* W2e = g_W2h + (size_t)e * Ii * Dd;
    uint32_t sb = smem_u32(smem);

    float c[4][8][4];
#pragma unroll
    for (int mf = 0; mf < 4; mf++)
#pragma unroll
        for (int nf = 0; nf < 8; nf++)
#pragma unroll
            for (int q = 0; q < 4; q++) c[mf][nf][q] = 0.f;

    auto load_stage = [&](int s, int it) {
        int k0 = it * 32;
        uint32_t da = sb + s * A_ST;
#pragma unroll
        for (int q = 0; q < 2; q++) {
            int j = tid + q * 256;
            int row = j >> 2, seg = j & 3;
            cp16(da + (uint32_t)(row * A_PITCH + seg * 16),
                 Ae + (size_t)row * Ii + k0 + seg * 8);
        }
        uint32_t db = sb + SM_B_OFF + s * B_ST;
#pragma unroll
        for (int q = 0; q < 4; q++) {
            int j = tid + q * 256;
            int r = j >> 5, cc = j & 31;
            cp16(db + (uint32_t)(r * B_PITCH + cc * 16),
                 W2e + (size_t)(k0 + r) * Dd + n0 + cc * 8);
        }
        CP_COMMIT();
    };

    auto compute_stage = [&](int s) {
        uint32_t sa = sb + s * A_ST;
        uint32_t sbB = sb + SM_B_OFF + s * B_ST;
#pragma unroll
        for (int ks = 0; ks < 2; ks++) {
            uint32_t a[4][4];
#pragma unroll
            for (int mf = 0; mf < 4; mf++) {
                uint32_t addr = sa
                    + (uint32_t)((wm * 64 + mf * 16 + (grp & 1) * 8 + r8) * A_PITCH
                                 + ks * 32 + (grp >> 1) * 16);
                ldsm_x4(a[mf][0], a[mf][1], a[mf][2], a[mf][3], addr);
            }
#pragma unroll
            for (int ch = 0; ch < 4; ch++) {
                uint32_t b0, b1, b2, b3;
                uint32_t addr = sbB
                    + (uint32_t)((ks * 16 + (grp & 1) * 8 + r8) * B_PITCH
                                 + wn * 128 + ch * 32 + (grp >> 1) * 16);
                ldsm_x4_t(b0, b1, b2, b3, addr);
                int nf0 = ch * 2, nf1 = ch * 2 + 1;
#pragma unroll
                for (int mf = 0; mf < 4; mf++) {
                    mma_f16(c[mf][nf0][0], c[mf][nf0][1], c[mf][nf0][2], c[mf][nf0][3],
                            a[mf][0], a[mf][1], a[mf][2], a[mf][3], b0, b1);
                    mma_f16(c[mf][nf1][0], c[mf][nf1][1], c[mf][nf1][2], c[mf][nf1][3],
                            a[mf][0], a[mf][1], a[mf][2], a[mf][3], b2, b3);
                }
            }
        }
    };

    load_stage(0, 0);
    load_stage(1, 1);
    for (int it = 0; it < NIT; it++) {
        int s = it % 3;
        if (it < NIT - 1) { CP_WAIT1(); } else { CP_WAIT0(); }
        __syncthreads();
        if (it + 2 < NIT) load_stage((it + 2) % 3, it + 2);
        compute_stage(s);
    }

#pragma unroll
    for (int mf = 0; mf < 4; mf++) {
#pragma unroll
        for (int nf = 0; nf < 8; nf++) {
            int row0 = m0 + wm * 64 + mf * 16 + lg;
            int col  = n0 + wn * 64 + nf * 8 + lt * 2;
            *(float2*)(g_Oe + ((size_t)e * CAP + row0) * Dd + col) =
                make_float2(c[mf][nf][0], c[mf][nf][1]);
            *(float2*)(g_Oe + ((size_t)e * CAP + row0 + 8) * Dd + col) =
                make_float2(c[mf][nf][2], c[mf][nf][3]);
        }
    }
}

// ---------------- 6) combine ----------------
__global__ __launch_bounds__(256) void combine_kernel(float* __restrict__ out) {
    int token = blockIdx.x;
    int s0 = token * 2, s1 = s0 + 1;
    int e0 = g_slot_e[s0], p0 = g_slot_pos[s0];
    int e1 = g_slot_e[s1], p1 = g_slot_pos[s1];
    float g0 = g_slot_gate[s0], g1 = g_slot_gate[s1];
    int i = threadIdx.x;
    float4 acc = make_float4(0.f, 0.f, 0.f, 0.f);
    if (p0 >= 0) {
        float4 v = *(const float4*)(g_Oe + ((size_t)e0 * CAP + p0) * Dd + i * 4);
        acc.x += g0 * v.x; acc.y += g0 * v.y; acc.z += g0 * v.z; acc.w += g0 * v.w;
    }
    if (p1 >= 0) {
        float4 v = *(const float4*)(g_Oe + ((size_t)e1 * CAP + p1) * Dd + i * 4);
        acc.x += g1 * v.x; acc.y += g1 * v.y; acc.z += g1 * v.z; acc.w += g1 * v.w;
    }
    *(float4*)(out + (size_t)token * Dd + i * 4) = acc;
}

// ---------------- launch ----------------
extern "C" void kernel_launch(void* const* d_in, const int* in_sizes, int n_in,
                              void* d_out, int out_size) {
    const float* x  = (const float*)d_in[0];
    const float* Wg = (const float*)d_in[1];
    const float* W1 = (const float*)d_in[2];
    const float* W2 = (const float*)d_in[3];
    float* out = (float*)d_out;

    void *pW1h, *pW2h;
    cudaGetSymbolAddress(&pW1h, g_W1h);
    cudaGetSymbolAddress(&pW2h, g_W2h);

    cudaFuncSetAttribute(gemm1_glu_kernel,
                         cudaFuncAttributeMaxDynamicSharedMemorySize, SMEM_TOT);
    cudaFuncSetAttribute(gemm2_kernel,
                         cudaFuncAttributeMaxDynamicSharedMemorySize, SMEM_TOT);

    // weight fp16 prepass
    {
        int n8_1 = (int)((size_t)Ee * Dd * TWOI / 8);   // 4,194,304
        int n8_2 = (int)((size_t)Ee * Ii * Dd / 8);     // 2,097,152
        to_half_kernel<<<(n8_1 + 255) / 256, 256>>>((const float4*)W1, (uint4*)pW1h, n8_1);
        to_half_kernel<<<(n8_2 + 255) / 256, 256>>>((const float4*)W2, (uint4*)pW2h, n8_2);
    }

    router_kernel<<<Nn / 8, 256>>>(x, Wg);
    scan_kernel<<<1, 1024>>>();
    gather_kernel<<<NS, 256>>>(x);
    gemm1_glu_kernel<<<dim3(Ii / 128, CAP / 128, Ee), 256, SMEM_TOT>>>();
    gemm2_kernel   <<<dim3(Dd / 256, CAP / 128, Ee), 256, SMEM_TOT>>>();
    combine_kernel<<<Nn, 256>>>(out);
}

// round 9
// speedup vs baseline: 2.0008x; 1.1253x over previous
#include <cuda_runtime.h>
#include <cuda_fp16.h>
#include <cstdint>

// ---------------- problem constants ----------------
constexpr int Dd   = 1024;     // hidden
constexpr int Ii   = 2048;     // GLU intermediate
constexpr int TWOI = 2 * Ii;   // 4096
constexpr int Ee   = 8;        // experts
constexpr int Nn   = 4096;     // tokens
constexpr int NS   = Nn * 2;   // slots
constexpr int CAP  = 1280;     // capacity

// ---------------- scratch ----------------
__device__ __half g_Xe[(size_t)Ee * CAP * Dd];    // 20 MB  dispatched inputs (fp16)
__device__ __half g_Hg[(size_t)Ee * CAP * Ii];    // 42 MB  post-GLU activations (fp16)
__device__ float  g_Oe[(size_t)Ee * CAP * Dd];    // 40 MB  expert outputs (fp32)
__device__ __half g_W1h[(size_t)Ee * Dd * TWOI];  // 64 MB  W1 fp16
__device__ __half g_W2h[(size_t)Ee * Ii * Dd];    // 32 MB  W2 fp16
__device__ int    g_slot_e[NS];
__device__ int    g_slot_pos[NS];                 // -1 if dropped
__device__ float  g_slot_gate[NS];
__device__ int    g_count[Ee];

// ---------------- helpers ----------------
__device__ __forceinline__ uint32_t smem_u32(const void* p) {
    uint32_t a;
    asm("{ .reg .u64 t; cvta.to.shared.u64 t, %1; cvt.u32.u64 %0, t; }" : "=r"(a) : "l"(p));
    return a;
}
__device__ __forceinline__ void cp16(uint32_t dst, const void* src) {
    asm volatile("cp.async.cg.shared.global [%0], [%1], 16;" :: "r"(dst), "l"(src));
}
#define CP_COMMIT() asm volatile("cp.async.commit_group;")
#define CP_WAIT1()  asm volatile("cp.async.wait_group 1;")
#define CP_WAIT0()  asm volatile("cp.async.wait_group 0;")

__device__ __forceinline__ void ldsm_x4(uint32_t& r0, uint32_t& r1, uint32_t& r2, uint32_t& r3,
                                        uint32_t addr) {
    asm volatile("ldmatrix.sync.aligned.m8n8.x4.shared.b16 {%0,%1,%2,%3}, [%4];"
        : "=r"(r0), "=r"(r1), "=r"(r2), "=r"(r3) : "r"(addr));
}
__device__ __forceinline__ void ldsm_x4_t(uint32_t& r0, uint32_t& r1, uint32_t& r2, uint32_t& r3,
                                          uint32_t addr) {
    asm volatile("ldmatrix.sync.aligned.m8n8.x4.trans.shared.b16 {%0,%1,%2,%3}, [%4];"
        : "=r"(r0), "=r"(r1), "=r"(r2), "=r"(r3) : "r"(addr));
}
__device__ __forceinline__ void mma_f16(float& c0, float& c1, float& c2, float& c3,
                                        uint32_t a0, uint32_t a1, uint32_t a2, uint32_t a3,
                                        uint32_t b0, uint32_t b1) {
    asm volatile(
        "mma.sync.aligned.m16n8k16.row.col.f32.f16.f16.f32 "
        "{%0,%1,%2,%3}, {%4,%5,%6,%7}, {%8,%9}, {%0,%1,%2,%3};\n"
        : "+f"(c0), "+f"(c1), "+f"(c2), "+f"(c3)
        : "r"(a0), "r"(a1), "r"(a2), "r"(a3), "r"(b0), "r"(b1));
}
__device__ __forceinline__ float gelu(float a) {
    return 0.5f * a * (1.0f + erff(a * 0.70710678118654752f));
}
__device__ __forceinline__ uint32_t packh2(float lo, float hi) {
    __half2 h = __floats2half2_rn(lo, hi);
    return *reinterpret_cast<uint32_t*>(&h);
}

// ---------------- smem layout ----------------
// A tile: 128 rows x 32 k halves (64B data), pitch 80B -> conflict-free ldmatrix
// B tiles: 32 k-rows, pitch = data + 16B  -> conflict-free ldmatrix.trans
constexpr int A_PITCH = 80;
constexpr int B_PITCH = 528;                   // 256 n-halves (GEMM1)
constexpr int A_ST = 128 * A_PITCH;            // 10240
constexpr int B_ST = 32 * B_PITCH;             // 16896
constexpr int SM_B_OFF = 3 * A_ST;             // 30720
constexpr int SMEM_TOT = SM_B_OFF + 3 * B_ST;  // 81408 (GEMM1)

constexpr int B2_PITCH = 272;                  // 128 n-halves (GEMM2)
constexpr int B2_ST = 32 * B2_PITCH;           // 8704
constexpr int G2_B_OFF = 3 * A_ST;             // 30720
constexpr int G2_SMEM = G2_B_OFF + 3 * B2_ST;  // 56832

// ---------------- 0) fp32 -> fp16 weight prepass ----------------
__global__ __launch_bounds__(256) void to_half_kernel(const float4* __restrict__ src,
                                                      uint4* __restrict__ dst, int n8) {
    int i = blockIdx.x * 256 + threadIdx.x;
    if (i >= n8) return;
    float4 a = src[2 * i], b = src[2 * i + 1];
    uint4 o;
    o.x = packh2(a.x, a.y);
    o.y = packh2(a.z, a.w);
    o.z = packh2(b.x, b.y);
    o.w = packh2(b.z, b.w);
    dst[i] = o;
}

// ---------------- 1) router ----------------
__global__ __launch_bounds__(256) void router_kernel(const float* __restrict__ x,
                                                     const float* __restrict__ Wg) {
    int warp = threadIdx.x >> 5, lane = threadIdx.x & 31;
    int token = blockIdx.x * 8 + warp;
    if (token >= Nn) return;
    const float* xr = x + (size_t)token * Dd;
    float acc[Ee];
#pragma unroll
    for (int e = 0; e < Ee; e++) acc[e] = 0.f;
    for (int k = lane; k < Dd; k += 32) {
        float xv = xr[k];
#pragma unroll
        for (int e = 0; e < Ee; e++) acc[e] += xv * Wg[e * Dd + k];
    }
#pragma unroll
    for (int e = 0; e < Ee; e++)
#pragma unroll
        for (int off = 16; off > 0; off >>= 1)
            acc[e] += __shfl_xor_sync(0xffffffffu, acc[e], off);
    if (lane == 0) {
        float v0 = -1e30f; int e0 = 0;
#pragma unroll
        for (int e = 0; e < Ee; e++) if (acc[e] > v0) { v0 = acc[e]; e0 = e; }
        float v1 = -1e30f; int e1 = 0;
#pragma unroll
        for (int e = 0; e < Ee; e++) if (e != e0 && acc[e] > v1) { v1 = acc[e]; e1 = e; }
        float t = expf(v1 - v0);
        int s = token * 2;
        g_slot_e[s] = e0; g_slot_e[s + 1] = e1;
        g_slot_gate[s]     = 1.0f / (1.0f + t);
        g_slot_gate[s + 1] = t / (1.0f + t);
    }
}

// ---------------- 2) capacity scan (shuffle-based, 2 syncthreads) ----------------
// 8 expert counters packed into 4 u32 (2 x 16-bit fields; totals <= 8192, no overflow)
__global__ __launch_bounds__(1024) void scan_kernel() {
    __shared__ uint32_t wsum[32][4];
    int t = threadIdx.x;
    int lane = t & 31, warp = t >> 5;

    int se[8];
    uint32_t pk[4] = {0u, 0u, 0u, 0u};
    int base = t * 8;
#pragma unroll
    for (int i = 0; i < 8; i++) {
        se[i] = g_slot_e[base + i];
        pk[se[i] >> 1] += 1u << ((se[i] & 1) * 16);
    }

    // warp-inclusive scan
    uint32_t inc[4];
#pragma unroll
    for (int j = 0; j < 4; j++) inc[j] = pk[j];
#pragma unroll
    for (int off = 1; off < 32; off <<= 1) {
#pragma unroll
        for (int j = 0; j < 4; j++) {
            uint32_t v = __shfl_up_sync(0xffffffffu, inc[j], off);
            if (lane >= off) inc[j] += v;
        }
    }
    if (lane == 31)
#pragma unroll
        for (int j = 0; j < 4; j++) wsum[warp][j] = inc[j];
    __syncthreads();

    // warp 0: inclusive scan over the 32 warp totals
    if (warp == 0) {
        uint32_t w[4];
#pragma unroll
        for (int j = 0; j < 4; j++) w[j] = wsum[lane][j];
#pragma unroll
        for (int off = 1; off < 32; off <<= 1) {
#pragma unroll
            for (int j = 0; j < 4; j++) {
                uint32_t v = __shfl_up_sync(0xffffffffu, w[j], off);
                if (lane >= off) w[j] += v;
            }
        }
#pragma unroll
        for (int j = 0; j < 4; j++) wsum[lane][j] = w[j];
        if (lane == 31) {
#pragma unroll
            for (int j = 0; j < 4; j++) {
                int c0 = (int)(w[j] & 0xFFFFu), c1 = (int)(w[j] >> 16);
                g_count[2 * j]     = (c0 < CAP) ? c0 : CAP;
                g_count[2 * j + 1] = (c1 < CAP) ? c1 : CAP;
            }
        }
    }
    __syncthreads();

    int run[Ee];
#pragma unroll
    for (int j = 0; j < 4; j++) {
        uint32_t wp = (warp > 0) ? wsum[warp - 1][j] : 0u;
        uint32_t ex = wp + inc[j] - pk[j];   // exclusive base, packed
        run[2 * j]     = (int)(ex & 0xFFFFu);
        run[2 * j + 1] = (int)(ex >> 16);
    }
#pragma unroll
    for (int i = 0; i < 8; i++) {
        int e = se[i];
        int p = 0;
#pragma unroll
        for (int j = 0; j < Ee; j++)
            if (e == j) { p = run[j]; run[j] = p + 1; }
        g_slot_pos[base + i] = (p < CAP) ? p : -1;
    }
}

// ---------------- 3) gather -> fp16 ----------------
__global__ __launch_bounds__(256) void gather_kernel(const float* __restrict__ x) {
    int s = blockIdx.x;
    int p = g_slot_pos[s];
    if (p < 0) return;
    int e = g_slot_e[s];
    int token = s >> 1;
    float4 v = ((const float4*)(x + (size_t)token * Dd))[threadIdx.x];
    uint2 u;
    u.x = packh2(v.x, v.y);
    u.y = packh2(v.z, v.w);
    *(uint2*)(g_Xe + ((size_t)e * CAP + p) * Dd + threadIdx.x * 4) = u;
}

// ---------------- 4) GEMM1 (fp16 mma, warp tile 64x64) + fused GLU ----------------
// Block: 128 rows x 256 cols (128 inp + 128 gate at matching n), K = 1024, BK = 32.
// 8 warps (2m x 4n). grid (Ii/128 = 16, CAP/128 = 10, Ee), 256 threads.
__global__ __launch_bounds__(256, 1) void gemm1_glu_kernel() {
    extern __shared__ __align__(16) char smem[];
    constexpr int NIT = Dd / 32;   // 32
    int e = blockIdx.z;
    int m0 = blockIdx.y * 128;
    if (m0 >= g_count[e]) return;
    int n0 = blockIdx.x * 128;

    int tid = threadIdx.x;
    int warp = tid >> 5, lane = tid & 31;
    int wm = warp & 1, wn = warp >> 1;        // 2m x 4n
    int lg = lane >> 2, lt = lane & 3;
    int r8 = lane & 7, grp = lane >> 3;

    const __half* Ae  = g_Xe + ((size_t)e * CAP + m0) * Dd;
    const __half* W1e = g_W1h + (size_t)e * Dd * TWOI;
    uint32_t sb = smem_u32(smem);

    float c[4][8][4];
#pragma unroll
    for (int mf = 0; mf < 4; mf++)
#pragma unroll
        for (int nf = 0; nf < 8; nf++)
#pragma unroll
            for (int q = 0; q < 4; q++) c[mf][nf][q] = 0.f;

    auto load_stage = [&](int s, int it) {
        int k0 = it * 32;
        uint32_t da = sb + s * A_ST;
#pragma unroll
        for (int q = 0; q < 2; q++) {
            int j = tid + q * 256;
            int row = j >> 2, seg = j & 3;
            cp16(da + (uint32_t)(row * A_PITCH + seg * 16),
                 Ae + (size_t)row * Dd + k0 + seg * 8);
        }
        uint32_t db = sb + SM_B_OFF + s * B_ST;
#pragma unroll
        for (int q = 0; q < 4; q++) {
            int j = tid + q * 256;
            int r = j >> 5, cc = j & 31;
            const __half* src = W1e + (size_t)(k0 + r) * TWOI + n0
                              + (cc & 15) * 8 + ((cc >> 4) ? Ii : 0);
            cp16(db + (uint32_t)(r * B_PITCH + cc * 16), src);
        }
        CP_COMMIT();
    };

    auto compute_stage = [&](int s) {
        uint32_t sa = sb + s * A_ST;
        uint32_t sbB = sb + SM_B_OFF + s * B_ST;
#pragma unroll
        for (int ks = 0; ks < 2; ks++) {
            uint32_t a[4][4];
#pragma unroll
            for (int mf = 0; mf < 4; mf++) {
                uint32_t addr = sa
                    + (uint32_t)((wm * 64 + mf * 16 + (grp & 1) * 8 + r8) * A_PITCH
                                 + ks * 32 + (grp >> 1) * 16);
                ldsm_x4(a[mf][0], a[mf][1], a[mf][2], a[mf][3], addr);
            }
#pragma unroll
            for (int ch = 0; ch < 4; ch++) {
                uint32_t b0, b1, b2, b3;
                uint32_t addr = sbB
                    + (uint32_t)((ks * 16 + (grp & 1) * 8 + r8) * B_PITCH
                                 + (ch >> 1) * 256 + wn * 64 + (ch & 1) * 32 + (grp >> 1) * 16);
                ldsm_x4_t(b0, b1, b2, b3, addr);
                int nf0 = ch * 2, nf1 = ch * 2 + 1;
#pragma unroll
                for (int mf = 0; mf < 4; mf++) {
                    mma_f16(c[mf][nf0][0], c[mf][nf0][1], c[mf][nf0][2], c[mf][nf0][3],
                            a[mf][0], a[mf][1], a[mf][2], a[mf][3], b0, b1);
                    mma_f16(c[mf][nf1][0], c[mf][nf1][1], c[mf][nf1][2], c[mf][nf1][3],
                            a[mf][0], a[mf][1], a[mf][2], a[mf][3], b2, b3);
                }
            }
        }
    };

    load_stage(0, 0);
    load_stage(1, 1);
    for (int it = 0; it < NIT; it++) {
        int s = it % 3;
        if (it < NIT - 1) { CP_WAIT1(); } else { CP_WAIT0(); }
        __syncthreads();
        if (it + 2 < NIT) load_stage((it + 2) % 3, it + 2);
        compute_stage(s);
    }

    // fused GLU epilogue: nf 0..3 = inp, nf+4 = gate at matching cols
#pragma unroll
    for (int mf = 0; mf < 4; mf++) {
#pragma unroll
        for (int nf = 0; nf < 4; nf++) {
            int row0 = m0 + wm * 64 + mf * 16 + lg;
            int col  = n0 + wn * 32 + nf * 8 + lt * 2;
            float* i4 = c[mf][nf];
            float* g4 = c[mf][nf + 4];
            uint32_t h01 = packh2(gelu(i4[0]) * g4[0], gelu(i4[1]) * g4[1]);
            uint32_t h23 = packh2(gelu(i4[2]) * g4[2], gelu(i4[3]) * g4[3]);
            *(uint32_t*)(g_Hg + ((size_t)e * CAP + row0) * Ii + col)       = h01;
            *(uint32_t*)(g_Hg + ((size_t)e * CAP + row0 + 8) * Ii + col)  = h23;
        }
    }
}

// ---------------- 5) GEMM2: Oe = Hg @ W2 (fp16 mma, 128x128 tile, 2 CTAs/SM) ----------------
// 4 warps (2m x 2n), warp tile 64x64, K = 2048, BK = 32.
// grid (Dd/128 = 8, CAP/128 = 10, Ee), 128 threads.
__global__ __launch_bounds__(128, 2) void gemm2_kernel() {
    extern __shared__ __align__(16) char smem[];
    constexpr int NIT = Ii / 32;   // 64
    int e = blockIdx.z;
    int m0 = blockIdx.y * 128;
    if (m0 >= g_count[e]) return;
    int n0 = blockIdx.x * 128;

    int tid = threadIdx.x;
    int warp = tid >> 5, lane = tid & 31;
    int wm = warp & 1, wn = warp >> 1;        // 2m x 2n
    int lg = lane >> 2, lt = lane & 3;
    int r8 = lane & 7, grp = lane >> 3;

    const __half* Ae  = g_Hg + ((size_t)e * CAP + m0) * Ii;
    const __half* W2e = g_W2h + (size_t)e * Ii * Dd;
    uint32_t sb = smem_u32(smem);

    float c[4][8][4];
#pragma unroll
    for (int mf = 0; mf < 4; mf++)
#pragma unroll
        for (int nf = 0; nf < 8; nf++)
#pragma unroll
            for (int q = 0; q < 4; q++) c[mf][nf][q] = 0.f;

    auto load_stage = [&](int s, int it) {
        int k0 = it * 32;
        uint32_t da = sb + s * A_ST;
#pragma unroll
        for (int q = 0; q < 4; q++) {
            int j = tid + q * 128;
            int row = j >> 2, seg = j & 3;
            cp16(da + (uint32_t)(row * A_PITCH + seg * 16),
                 Ae + (size_t)row * Ii + k0 + seg * 8);
        }
        uint32_t db = sb + G2_B_OFF + s * B2_ST;
#pragma unroll
        for (int q = 0; q < 4; q++) {
            int j = tid + q * 128;
            int r = j >> 4, cc = j & 15;
            cp16(db + (uint32_t)(r * B2_PITCH + cc * 16),
                 W2e + (size_t)(k0 + r) * Dd + n0 + cc * 8);
        }
        CP_COMMIT();
    };

    auto compute_stage = [&](int s) {
        uint32_t sa = sb + s * A_ST;
        uint32_t sbB = sb + G2_B_OFF + s * B2_ST;
#pragma unroll
        for (int ks = 0; ks < 2; ks++) {
            uint32_t a[4][4];
#pragma unroll
            for (int mf = 0; mf < 4; mf++) {
                uint32_t addr = sa
                    + (uint32_t)((wm * 64 + mf * 16 + (grp & 1) * 8 + r8) * A_PITCH
                                 + ks * 32 + (grp >> 1) * 16);
                ldsm_x4(a[mf][0], a[mf][1], a[mf][2], a[mf][3], addr);
            }
#pragma unroll
            for (int ch = 0; ch < 4; ch++) {
                uint32_t b0, b1, b2, b3;
                uint32_t addr = sbB
                    + (uint32_t)((ks * 16 + (grp & 1) * 8 + r8) * B2_PITCH
                                 + wn * 128 + ch * 32 + (grp >> 1) * 16);
                ldsm_x4_t(b0, b1, b2, b3, addr);
                int nf0 = ch * 2, nf1 = ch * 2 + 1;
#pragma unroll
                for (int mf = 0; mf < 4; mf++) {
                    mma_f16(c[mf][nf0][0], c[mf][nf0][1], c[mf][nf0][2], c[mf][nf0][3],
                            a[mf][0], a[mf][1], a[mf][2], a[mf][3], b0, b1);
                    mma_f16(c[mf][nf1][0], c[mf][nf1][1], c[mf][nf1][2], c[mf][nf1][3],
                            a[mf][0], a[mf][1], a[mf][2], a[mf][3], b2, b3);
                }
            }
        }
    };

    load_stage(0, 0);
    load_stage(1, 1);
    for (int it = 0; it < NIT; it++) {
        int s = it % 3;
        if (it < NIT - 1) { CP_WAIT1(); } else { CP_WAIT0(); }
        __syncthreads();
        if (it + 2 < NIT) load_stage((it + 2) % 3, it + 2);
        compute_stage(s);
    }

#pragma unroll
    for (int mf = 0; mf < 4; mf++) {
#pragma unroll
        for (int nf = 0; nf < 8; nf++) {
            int row0 = m0 + wm * 64 + mf * 16 + lg;
            int col  = n0 + wn * 64 + nf * 8 + lt * 2;
            *(float2*)(g_Oe + ((size_t)e * CAP + row0) * Dd + col) =
                make_float2(c[mf][nf][0], c[mf][nf][1]);
            *(float2*)(g_Oe + ((size_t)e * CAP + row0 + 8) * Dd + col) =
                make_float2(c[mf][nf][2], c[mf][nf][3]);
        }
    }
}

// ---------------- 6) combine ----------------
__global__ __launch_bounds__(256) void combine_kernel(float* __restrict__ out) {
    int token = blockIdx.x;
    int s0 = token * 2, s1 = s0 + 1;
    int e0 = g_slot_e[s0], p0 = g_slot_pos[s0];
    int e1 = g_slot_e[s1], p1 = g_slot_pos[s1];
    float g0 = g_slot_gate[s0], g1 = g_slot_gate[s1];
    int i = threadIdx.x;
    float4 acc = make_float4(0.f, 0.f, 0.f, 0.f);
    if (p0 >= 0) {
        float4 v = *(const float4*)(g_Oe + ((size_t)e0 * CAP + p0) * Dd + i * 4);
        acc.x += g0 * v.x; acc.y += g0 * v.y; acc.z += g0 * v.z; acc.w += g0 * v.w;
    }
    if (p1 >= 0) {
        float4 v = *(const float4*)(g_Oe + ((size_t)e1 * CAP + p1) * Dd + i * 4);
        acc.x += g1 * v.x; acc.y += g1 * v.y; acc.z += g1 * v.z; acc.w += g1 * v.w;
    }
    *(float4*)(out + (size_t)token * Dd + i * 4) = acc;
}

// ---------------- launch ----------------
extern "C" void kernel_launch(void* const* d_in, const int* in_sizes, int n_in,
                              void* d_out, int out_size) {
    const float* x  = (const float*)d_in[0];
    const float* Wg = (const float*)d_in[1];
    const float* W1 = (const float*)d_in[2];
    const float* W2 = (const float*)d_in[3];
    float* out = (float*)d_out;

    void *pW1h, *pW2h;
    cudaGetSymbolAddress(&pW1h, g_W1h);
    cudaGetSymbolAddress(&pW2h, g_W2h);

    cudaFuncSetAttribute(gemm1_glu_kernel,
                         cudaFuncAttributeMaxDynamicSharedMemorySize, SMEM_TOT);
    cudaFuncSetAttribute(gemm2_kernel,
                         cudaFuncAttributeMaxDynamicSharedMemorySize, G2_SMEM);

    // weight fp16 prepass
    {
        int n8_1 = (int)((size_t)Ee * Dd * TWOI / 8);
        int n8_2 = (int)((size_t)Ee * Ii * Dd / 8);
        to_half_kernel<<<(n8_1 + 255) / 256, 256>>>((const float4*)W1, (uint4*)pW1h, n8_1);
        to_half_kernel<<<(n8_2 + 255) / 256, 256>>>((const float4*)W2, (uint4*)pW2h, n8_2);
    }

    router_kernel<<<Nn / 8, 256>>>(x, Wg);
    scan_kernel<<<1, 1024>>>();
    gather_kernel<<<NS, 256>>>(x);
    gemm1_glu_kernel<<<dim3(Ii / 128, CAP / 128, Ee), 256, SMEM_TOT>>>();
    gemm2_kernel   <<<dim3(Dd / 128, CAP / 128, Ee), 128, G2_SMEM>>>();
    combine_kernel<<<Nn, 256>>>(out);
}

// round 10
// speedup vs baseline: 2.3416x; 1.1703x over previous
#include <cuda_runtime.h>
#include <cuda_fp16.h>
#include <cstdint>

// ---------------- problem constants ----------------
constexpr int Dd   = 1024;     // hidden
constexpr int Ii   = 2048;     // GLU intermediate
constexpr int TWOI = 2 * Ii;   // 4096
constexpr int Ee   = 8;        // experts
constexpr int Nn   = 4096;     // tokens
constexpr int NS   = Nn * 2;   // slots
constexpr int CAP  = 1280;     // capacity

// ---------------- scratch ----------------
__device__ __half g_Xe[(size_t)Ee * CAP * Dd];    // 20 MB  dispatched inputs (fp16)
__device__ __half g_Hg[(size_t)Ee * CAP * Ii];    // 42 MB  post-GLU activations (fp16)
__device__ float  g_Oe[(size_t)Ee * CAP * Dd];    // 40 MB  expert outputs (fp32)
__device__ __half g_W1h[(size_t)Ee * Dd * TWOI];  // 64 MB  W1 fp16
__device__ __half g_W2h[(size_t)Ee * Ii * Dd];    // 32 MB  W2 fp16
__device__ int    g_slot_e[NS];
__device__ int    g_slot_pos[NS];                 // -1 if dropped
__device__ float  g_slot_gate[NS];
__device__ int    g_count[Ee];

// ---------------- helpers ----------------
__device__ __forceinline__ uint32_t smem_u32(const void* p) {
    uint32_t a;
    asm("{ .reg .u64 t; cvta.to.shared.u64 t, %1; cvt.u32.u64 %0, t; }" : "=r"(a) : "l"(p));
    return a;
}
__device__ __forceinline__ void cp16(uint32_t dst, const void* src) {
    asm volatile("cp.async.cg.shared.global [%0], [%1], 16;" :: "r"(dst), "l"(src));
}
#define CP_COMMIT() asm volatile("cp.async.commit_group;")
#define CP_WAIT1()  asm volatile("cp.async.wait_group 1;")
#define CP_WAIT0()  asm volatile("cp.async.wait_group 0;")

__device__ __forceinline__ void ldsm_x4(uint32_t& r0, uint32_t& r1, uint32_t& r2, uint32_t& r3,
                                        uint32_t addr) {
    asm volatile("ldmatrix.sync.aligned.m8n8.x4.shared.b16 {%0,%1,%2,%3}, [%4];"
        : "=r"(r0), "=r"(r1), "=r"(r2), "=r"(r3) : "r"(addr));
}
__device__ __forceinline__ void ldsm_x4_t(uint32_t& r0, uint32_t& r1, uint32_t& r2, uint32_t& r3,
                                          uint32_t addr) {
    asm volatile("ldmatrix.sync.aligned.m8n8.x4.trans.shared.b16 {%0,%1,%2,%3}, [%4];"
        : "=r"(r0), "=r"(r1), "=r"(r2), "=r"(r3) : "r"(addr));
}
__device__ __forceinline__ void mma_f16(float& c0, float& c1, float& c2, float& c3,
                                        uint32_t a0, uint32_t a1, uint32_t a2, uint32_t a3,
                                        uint32_t b0, uint32_t b1) {
    asm volatile(
        "mma.sync.aligned.m16n8k16.row.col.f32.f16.f16.f32 "
        "{%0,%1,%2,%3}, {%4,%5,%6,%7}, {%8,%9}, {%0,%1,%2,%3};\n"
        : "+f"(c0), "+f"(c1), "+f"(c2), "+f"(c3)
        : "r"(a0), "r"(a1), "r"(a2), "r"(a3), "r"(b0), "r"(b1));
}
__device__ __forceinline__ float gelu(float a) {
    return 0.5f * a * (1.0f + erff(a * 0.70710678118654752f));
}
__device__ __forceinline__ uint32_t packh2(float lo, float hi) {
    __half2 h = __floats2half2_rn(lo, hi);
    return *reinterpret_cast<uint32_t*>(&h);
}

// ---------------- smem layout ----------------
// A tile: 128 rows x 32 k halves (64B data), pitch 80B -> conflict-free ldmatrix
// B tile: 32 k-rows x 128 n halves (256B data), pitch 272B -> conflict-free ldmatrix.trans
constexpr int A_PITCH = 80;
constexpr int A_ST = 128 * A_PITCH;            // 10240
constexpr int B_PITCH = 272;
constexpr int B_ST = 32 * B_PITCH;             // 8704
constexpr int SM_B_OFF = 3 * A_ST;             // 30720
constexpr int SMEM_TOT = SM_B_OFF + 3 * B_ST;  // 56832  (both GEMMs)

// ---------------- 0) fp32 -> fp16 weight prepass ----------------
__global__ __launch_bounds__(256) void to_half_kernel(const float4* __restrict__ src,
                                                      uint4* __restrict__ dst, int n8) {
    int i = blockIdx.x * 256 + threadIdx.x;
    if (i >= n8) return;
    float4 a = src[2 * i], b = src[2 * i + 1];
    uint4 o;
    o.x = packh2(a.x, a.y);
    o.y = packh2(a.z, a.w);
    o.z = packh2(b.x, b.y);
    o.w = packh2(b.z, b.w);
    dst[i] = o;
}

// ---------------- 1) router ----------------
__global__ __launch_bounds__(256) void router_kernel(const float* __restrict__ x,
                                                     const float* __restrict__ Wg) {
    int warp = threadIdx.x >> 5, lane = threadIdx.x & 31;
    int token = blockIdx.x * 8 + warp;
    if (token >= Nn) return;
    const float* xr = x + (size_t)token * Dd;
    float acc[Ee];
#pragma unroll
    for (int e = 0; e < Ee; e++) acc[e] = 0.f;
    for (int k = lane; k < Dd; k += 32) {
        float xv = xr[k];
#pragma unroll
        for (int e = 0; e < Ee; e++) acc[e] += xv * Wg[e * Dd + k];
    }
#pragma unroll
    for (int e = 0; e < Ee; e++)
#pragma unroll
        for (int off = 16; off > 0; off >>= 1)
            acc[e] += __shfl_xor_sync(0xffffffffu, acc[e], off);
    if (lane == 0) {
        float v0 = -1e30f; int e0 = 0;
#pragma unroll
        for (int e = 0; e < Ee; e++) if (acc[e] > v0) { v0 = acc[e]; e0 = e; }
        float v1 = -1e30f; int e1 = 0;
#pragma unroll
        for (int e = 0; e < Ee; e++) if (e != e0 && acc[e] > v1) { v1 = acc[e]; e1 = e; }
        float t = expf(v1 - v0);
        int s = token * 2;
        g_slot_e[s] = e0; g_slot_e[s + 1] = e1;
        g_slot_gate[s]     = 1.0f / (1.0f + t);
        g_slot_gate[s + 1] = t / (1.0f + t);
    }
}

// ---------------- 2) capacity scan (shuffle-based, 2 syncthreads) ----------------
__global__ __launch_bounds__(1024) void scan_kernel() {
    __shared__ uint32_t wsum[32][4];
    int t = threadIdx.x;
    int lane = t & 31, warp = t >> 5;

    int se[8];
    uint32_t pk[4] = {0u, 0u, 0u, 0u};
    int base = t * 8;
#pragma unroll
    for (int i = 0; i < 8; i++) {
        se[i] = g_slot_e[base + i];
        pk[se[i] >> 1] += 1u << ((se[i] & 1) * 16);
    }

    uint32_t inc[4];
#pragma unroll
    for (int j = 0; j < 4; j++) inc[j] = pk[j];
#pragma unroll
    for (int off = 1; off < 32; off <<= 1) {
#pragma unroll
        for (int j = 0; j < 4; j++) {
            uint32_t v = __shfl_up_sync(0xffffffffu, inc[j], off);
            if (lane >= off) inc[j] += v;
        }
    }
    if (lane == 31)
#pragma unroll
        for (int j = 0; j < 4; j++) wsum[warp][j] = inc[j];
    __syncthreads();

    if (warp == 0) {
        uint32_t w[4];
#pragma unroll
        for (int j = 0; j < 4; j++) w[j] = wsum[lane][j];
#pragma unroll
        for (int off = 1; off < 32; off <<= 1) {
#pragma unroll
            for (int j = 0; j < 4; j++) {
                uint32_t v = __shfl_up_sync(0xffffffffu, w[j], off);
                if (lane >= off) w[j] += v;
            }
        }
#pragma unroll
        for (int j = 0; j < 4; j++) wsum[lane][j] = w[j];
        if (lane == 31) {
#pragma unroll
            for (int j = 0; j < 4; j++) {
                int c0 = (int)(w[j] & 0xFFFFu), c1 = (int)(w[j] >> 16);
                g_count[2 * j]     = (c0 < CAP) ? c0 : CAP;
                g_count[2 * j + 1] = (c1 < CAP) ? c1 : CAP;
            }
        }
    }
    __syncthreads();

    int run[Ee];
#pragma unroll
    for (int j = 0; j < 4; j++) {
        uint32_t wp = (warp > 0) ? wsum[warp - 1][j] : 0u;
        uint32_t ex = wp + inc[j] - pk[j];
        run[2 * j]     = (int)(ex & 0xFFFFu);
        run[2 * j + 1] = (int)(ex >> 16);
    }
#pragma unroll
    for (int i = 0; i < 8; i++) {
        int e = se[i];
        int p = 0;
#pragma unroll
        for (int j = 0; j < Ee; j++)
            if (e == j) { p = run[j]; run[j] = p + 1; }
        g_slot_pos[base + i] = (p < CAP) ? p : -1;
    }
}

// ---------------- 3) gather -> fp16 ----------------
__global__ __launch_bounds__(256) void gather_kernel(const float* __restrict__ x) {
    int s = blockIdx.x;
    int p = g_slot_pos[s];
    if (p < 0) return;
    int e = g_slot_e[s];
    int token = s >> 1;
    float4 v = ((const float4*)(x + (size_t)token * Dd))[threadIdx.x];
    uint2 u;
    u.x = packh2(v.x, v.y);
    u.y = packh2(v.z, v.w);
    *(uint2*)(g_Xe + ((size_t)e * CAP + p) * Dd + threadIdx.x * 4) = u;
}

// ---------------- 4) GEMM1 (fp16 mma, 128x128 tile, 2 CTAs/SM) + fused GLU ----------------
// Block: 128 rows x (64 inp + 64 gate cols, interleaved per warp), K = 1024, BK = 32.
// 4 warps (2m x 2n), warp tile 64x64 (32 inp + 32 gate n-halves).
// grid (Ii/64 = 32, CAP/128 = 10, Ee), 128 threads.
__global__ __launch_bounds__(128, 2) void gemm1_glu_kernel() {
    extern __shared__ __align__(16) char smem[];
    constexpr int NIT = Dd / 32;   // 32
    int e = blockIdx.z;
    int m0 = blockIdx.y * 128;
    if (m0 >= g_count[e]) return;
    int n0 = blockIdx.x * 64;

    int tid = threadIdx.x;
    int warp = tid >> 5, lane = tid & 31;
    int wm = warp & 1, wn = warp >> 1;        // 2m x 2n
    int lg = lane >> 2, lt = lane & 3;
    int r8 = lane & 7, grp = lane >> 3;

    const __half* Ae  = g_Xe + ((size_t)e * CAP + m0) * Dd;
    const __half* W1e = g_W1h + (size_t)e * Dd * TWOI;
    uint32_t sb = smem_u32(smem);

    float c[4][8][4];
#pragma unroll
    for (int mf = 0; mf < 4; mf++)
#pragma unroll
        for (int nf = 0; nf < 8; nf++)
#pragma unroll
            for (int q = 0; q < 4; q++) c[mf][nf][q] = 0.f;

    auto load_stage = [&](int s, int it) {
        int k0 = it * 32;
        uint32_t da = sb + s * A_ST;
#pragma unroll
        for (int q = 0; q < 4; q++) {
            int j = tid + q * 128;
            int row = j >> 2, seg = j & 3;
            cp16(da + (uint32_t)(row * A_PITCH + seg * 16),
                 Ae + (size_t)row * Dd + k0 + seg * 8);
        }
        uint32_t db = sb + SM_B_OFF + s * B_ST;
        // chunk cc (0..15): warp_n = cc>>3, inp cols if !(cc&4), else gate (+Ii)
#pragma unroll
        for (int q = 0; q < 4; q++) {
            int j = tid + q * 128;
            int r = j >> 4, cc = j & 15;
            const __half* src = W1e + (size_t)(k0 + r) * TWOI + n0
                              + (cc >> 3) * 32 + (cc & 3) * 8 + ((cc & 4) ? Ii : 0);
            cp16(db + (uint32_t)(r * B_PITCH + cc * 16), src);
        }
        CP_COMMIT();
    };

    auto compute_stage = [&](int s) {
        uint32_t sa = sb + s * A_ST;
        uint32_t sbB = sb + SM_B_OFF + s * B_ST;
#pragma unroll
        for (int ks = 0; ks < 2; ks++) {
            uint32_t a[4][4];
#pragma unroll
            for (int mf = 0; mf < 4; mf++) {
                uint32_t addr = sa
                    + (uint32_t)((wm * 64 + mf * 16 + (grp & 1) * 8 + r8) * A_PITCH
                                 + ks * 32 + (grp >> 1) * 16);
                ldsm_x4(a[mf][0], a[mf][1], a[mf][2], a[mf][3], addr);
            }
#pragma unroll
            for (int ch = 0; ch < 4; ch++) {
                uint32_t b0, b1, b2, b3;
                uint32_t addr = sbB
                    + (uint32_t)((ks * 16 + (grp & 1) * 8 + r8) * B_PITCH
                                 + wn * 128 + ch * 32 + (grp >> 1) * 16);
                ldsm_x4_t(b0, b1, b2, b3, addr);
                int nf0 = ch * 2, nf1 = ch * 2 + 1;
#pragma unroll
                for (int mf = 0; mf < 4; mf++) {
                    mma_f16(c[mf][nf0][0], c[mf][nf0][1], c[mf][nf0][2], c[mf][nf0][3],
                            a[mf][0], a[mf][1], a[mf][2], a[mf][3], b0, b1);
                    mma_f16(c[mf][nf1][0], c[mf][nf1][1], c[mf][nf1][2], c[mf][nf1][3],
                            a[mf][0], a[mf][1], a[mf][2], a[mf][3], b2, b3);
                }
            }
        }
    };

    load_stage(0, 0);
    load_stage(1, 1);
    for (int it = 0; it < NIT; it++) {
        int s = it % 3;
        if (it < NIT - 1) { CP_WAIT1(); } else { CP_WAIT0(); }
        __syncthreads();
        if (it + 2 < NIT) load_stage((it + 2) % 3, it + 2);
        compute_stage(s);
    }

    // fused GLU epilogue: nf 0..3 = inp (warp halves 0..31), nf+4 = gate, same cols
#pragma unroll
    for (int mf = 0; mf < 4; mf++) {
#pragma unroll
        for (int nf = 0; nf < 4; nf++) {
            int row0 = m0 + wm * 64 + mf * 16 + lg;
            int col  = n0 + wn * 32 + nf * 8 + lt * 2;
            float* i4 = c[mf][nf];
            float* g4 = c[mf][nf + 4];
            uint32_t h01 = packh2(gelu(i4[0]) * g4[0], gelu(i4[1]) * g4[1]);
            uint32_t h23 = packh2(gelu(i4[2]) * g4[2], gelu(i4[3]) * g4[3]);
            *(uint32_t*)(g_Hg + ((size_t)e * CAP + row0) * Ii + col)      = h01;
            *(uint32_t*)(g_Hg + ((size_t)e * CAP + row0 + 8) * Ii + col) = h23;
        }
    }
}

// ---------------- 5) GEMM2: Oe = Hg @ W2 (fp16 mma, 128x128 tile, 2 CTAs/SM) ----------------
// 4 warps (2m x 2n), warp tile 64x64, K = 2048, BK = 32.
// grid (Dd/128 = 8, CAP/128 = 10, Ee), 128 threads.
__global__ __launch_bounds__(128, 2) void gemm2_kernel() {
    extern __shared__ __align__(16) char smem[];
    constexpr int NIT = Ii / 32;   // 64
    int e = blockIdx.z;
    int m0 = blockIdx.y * 128;
    if (m0 >= g_count[e]) return;
    int n0 = blockIdx.x * 128;

    int tid = threadIdx.x;
    int warp = tid >> 5, lane = tid & 31;
    int wm = warp & 1, wn = warp >> 1;
    int lg = lane >> 2, lt = lane & 3;
    int r8 = lane & 7, grp = lane >> 3;

    const __half* Ae  = g_Hg + ((size_t)e * CAP + m0) * Ii;
    const __half* W2e = g_W2h + (size_t)e * Ii * Dd;
    uint32_t sb = smem_u32(smem);

    float c[4][8][4];
#pragma unroll
    for (int mf = 0; mf < 4; mf++)
#pragma unroll
        for (int nf = 0; nf < 8; nf++)
#pragma unroll
            for (int q = 0; q < 4; q++) c[mf][nf][q] = 0.f;

    auto load_stage = [&](int s, int it) {
        int k0 = it * 32;
        uint32_t da = sb + s * A_ST;
#pragma unroll
        for (int q = 0; q < 4; q++) {
            int j = tid + q * 128;
            int row = j >> 2, seg = j & 3;
            cp16(da + (uint32_t)(row * A_PITCH + seg * 16),
                 Ae + (size_t)row * Ii + k0 + seg * 8);
        }
        uint32_t db = sb + SM_B_OFF + s * B_ST;
#pragma unroll
        for (int q = 0; q < 4; q++) {
            int j = tid + q * 128;
            int r = j >> 4, cc = j & 15;
            cp16(db + (uint32_t)(r * B_PITCH + cc * 16),
                 W2e + (size_t)(k0 + r) * Dd + n0 + cc * 8);
        }
        CP_COMMIT();
    };

    auto compute_stage = [&](int s) {
        uint32_t sa = sb + s * A_ST;
        uint32_t sbB = sb + SM_B_OFF + s * B_ST;
#pragma unroll
        for (int ks = 0; ks < 2; ks++) {
            uint32_t a[4][4];
#pragma unroll
            for (int mf = 0; mf < 4; mf++) {
                uint32_t addr = sa
                    + (uint32_t)((wm * 64 + mf * 16 + (grp & 1) * 8 + r8) * A_PITCH
                                 + ks * 32 + (grp >> 1) * 16);
                ldsm_x4(a[mf][0], a[mf][1], a[mf][2], a[mf][3], addr);
            }
#pragma unroll
            for (int ch = 0; ch < 4; ch++) {
                uint32_t b0, b1, b2, b3;
                uint32_t addr = sbB
                    + (uint32_t)((ks * 16 + (grp & 1) * 8 + r8) * B_PITCH
                                 + wn * 128 + ch * 32 + (grp >> 1) * 16);
                ldsm_x4_t(b0, b1, b2, b3, addr);
                int nf0 = ch * 2, nf1 = ch * 2 + 1;
#pragma unroll
                for (int mf = 0; mf < 4; mf++) {
                    mma_f16(c[mf][nf0][0], c[mf][nf0][1], c[mf][nf0][2], c[mf][nf0][3],
                            a[mf][0], a[mf][1], a[mf][2], a[mf][3], b0, b1);
                    mma_f16(c[mf][nf1][0], c[mf][nf1][1], c[mf][nf1][2], c[mf][nf1][3],
                            a[mf][0], a[mf][1], a[mf][2], a[mf][3], b2, b3);
                }
            }
        }
    };

    load_stage(0, 0);
    load_stage(1, 1);
    for (int it = 0; it < NIT; it++) {
        int s = it % 3;
        if (it < NIT - 1) { CP_WAIT1(); } else { CP_WAIT0(); }
        __syncthreads();
        if (it + 2 < NIT) load_stage((it + 2) % 3, it + 2);
        compute_stage(s);
    }

#pragma unroll
    for (int mf = 0; mf < 4; mf++) {
#pragma unroll
        for (int nf = 0; nf < 8; nf++) {
            int row0 = m0 + wm * 64 + mf * 16 + lg;
            int col  = n0 + wn * 64 + nf * 8 + lt * 2;
            *(float2*)(g_Oe + ((size_t)e * CAP + row0) * Dd + col) =
                make_float2(c[mf][nf][0], c[mf][nf][1]);
            *(float2*)(g_Oe + ((size_t)e * CAP + row0 + 8) * Dd + col) =
                make_float2(c[mf][nf][2], c[mf][nf][3]);
        }
    }
}

// ---------------- 6) combine ----------------
__global__ __launch_bounds__(256) void combine_kernel(float* __restrict__ out) {
    int token = blockIdx.x;
    int s0 = token * 2, s1 = s0 + 1;
    int e0 = g_slot_e[s0], p0 = g_slot_pos[s0];
    int e1 = g_slot_e[s1], p1 = g_slot_pos[s1];
    float g0 = g_slot_gate[s0], g1 = g_slot_gate[s1];
    int i = threadIdx.x;
    float4 acc = make_float4(0.f, 0.f, 0.f, 0.f);
    if (p0 >= 0) {
        float4 v = *(const float4*)(g_Oe + ((size_t)e0 * CAP + p0) * Dd + i * 4);
        acc.x += g0 * v.x; acc.y += g0 * v.y; acc.z += g0 * v.z; acc.w += g0 * v.w;
    }
    if (p1 >= 0) {
        float4 v = *(const float4*)(g_Oe + ((size_t)e1 * CAP + p1) * Dd + i * 4);
        acc.x += g1 * v.x; acc.y += g1 * v.y; acc.z += g1 * v.z; acc.w += g1 * v.w;
    }
    *(float4*)(out + (size_t)token * Dd + i * 4) = acc;
}

// ---------------- launch ----------------
extern "C" void kernel_launch(void* const* d_in, const int* in_sizes, int n_in,
                              void* d_out, int out_size) {
    const float* x  = (const float*)d_in[0];
    const float* Wg = (const float*)d_in[1];
    const float* W1 = (const float*)d_in[2];
    const float* W2 = (const float*)d_in[3];
    float* out = (float*)d_out;

    void *pW1h, *pW2h;
    cudaGetSymbolAddress(&pW1h, g_W1h);
    cudaGetSymbolAddress(&pW2h, g_W2h);

    cudaFuncSetAttribute(gemm1_glu_kernel,
                         cudaFuncAttributeMaxDynamicSharedMemorySize, SMEM_TOT);
    cudaFuncSetAttribute(gemm2_kernel,
                         cudaFuncAttributeMaxDynamicSharedMemorySize, SMEM_TOT);

    // weight fp16 prepass
    {
        int n8_1 = (int)((size_t)Ee * Dd * TWOI / 8);
        int n8_2 = (int)((size_t)Ee * Ii * Dd / 8);
        to_half_kernel<<<(n8_1 + 255) / 256, 256>>>((const float4*)W1, (uint4*)pW1h, n8_1);
        to_half_kernel<<<(n8_2 + 255) / 256, 256>>>((const float4*)W2, (uint4*)pW2h, n8_2);
    }

    router_kernel<<<Nn / 8, 256>>>(x, Wg);
    scan_kernel<<<1, 1024>>>();
    gather_kernel<<<NS, 256>>>(x);
    gemm1_glu_kernel<<<dim3(Ii / 64, CAP / 128, Ee), 128, SMEM_TOT>>>();
    gemm2_kernel   <<<dim3(Dd / 128, CAP / 128, Ee), 128, SMEM_TOT>>>();
    combine_kernel<<<Nn, 256>>>(out);
}

// round 15
// speedup vs baseline: 2.4091x; 1.0288x over previous
#include <cuda_runtime.h>
#include <cuda_fp16.h>
#include <cstdint>

// ---------------- problem constants ----------------
constexpr int Dd   = 1024;     // hidden
constexpr int Ii   = 2048;     // GLU intermediate
constexpr int TWOI = 2 * Ii;   // 4096
constexpr int Ee   = 8;        // experts
constexpr int Nn   = 4096;     // tokens
constexpr int NS   = Nn * 2;   // slots
constexpr int CAP  = 1280;     // capacity

// ---------------- scratch ----------------
__device__ __half g_Xe[(size_t)Ee * CAP * Dd];    // 20 MB  dispatched inputs (fp16)
__device__ __half g_Hg[(size_t)Ee * CAP * Ii];    // 42 MB  post-GLU activations (fp16)
__device__ float  g_Oe[(size_t)Ee * CAP * Dd];    // 40 MB  expert outputs (fp32)
__device__ __half g_W1h[(size_t)Ee * Dd * TWOI];  // 64 MB  W1 fp16
__device__ __half g_W2h[(size_t)Ee * Ii * Dd];    // 32 MB  W2 fp16
__device__ int    g_slot_e[NS];
__device__ int    g_slot_pos[NS];                 // -1 if dropped
__device__ float  g_slot_gate[NS];
__device__ int    g_count[Ee];

// ---------------- helpers ----------------
__device__ __forceinline__ uint32_t smem_u32(const void* p) {
    uint32_t a;
    asm("{ .reg .u64 t; cvta.to.shared.u64 t, %1; cvt.u32.u64 %0, t; }" : "=r"(a) : "l"(p));
    return a;
}
__device__ __forceinline__ void cp16(uint32_t dst, const void* src) {
    asm volatile("cp.async.cg.shared.global [%0], [%1], 16;" :: "r"(dst), "l"(src));
}
#define CP_COMMIT() asm volatile("cp.async.commit_group;")
#define CP_WAIT1()  asm volatile("cp.async.wait_group 1;")
#define CP_WAIT0()  asm volatile("cp.async.wait_group 0;")

__device__ __forceinline__ void ldsm_x4(uint32_t& r0, uint32_t& r1, uint32_t& r2, uint32_t& r3,
                                        uint32_t addr) {
    asm volatile("ldmatrix.sync.aligned.m8n8.x4.shared.b16 {%0,%1,%2,%3}, [%4];"
        : "=r"(r0), "=r"(r1), "=r"(r2), "=r"(r3) : "r"(addr));
}
__device__ __forceinline__ void ldsm_x4_t(uint32_t& r0, uint32_t& r1, uint32_t& r2, uint32_t& r3,
                                          uint32_t addr) {
    asm volatile("ldmatrix.sync.aligned.m8n8.x4.trans.shared.b16 {%0,%1,%2,%3}, [%4];"
        : "=r"(r0), "=r"(r1), "=r"(r2), "=r"(r3) : "r"(addr));
}
__device__ __forceinline__ void mma_f16(float& c0, float& c1, float& c2, float& c3,
                                        uint32_t a0, uint32_t a1, uint32_t a2, uint32_t a3,
                                        uint32_t b0, uint32_t b1) {
    asm volatile(
        "mma.sync.aligned.m16n8k16.row.col.f32.f16.f16.f32 "
        "{%0,%1,%2,%3}, {%4,%5,%6,%7}, {%8,%9}, {%0,%1,%2,%3};\n"
        : "+f"(c0), "+f"(c1), "+f"(c2), "+f"(c3)
        : "r"(a0), "r"(a1), "r"(a2), "r"(a3), "r"(b0), "r"(b1));
}
__device__ __forceinline__ float gelu(float a) {
    return 0.5f * a * (1.0f + erff(a * 0.70710678118654752f));
}
__device__ __forceinline__ uint32_t packh2(float lo, float hi) {
    __half2 h = __floats2half2_rn(lo, hi);
    return *reinterpret_cast<uint32_t*>(&h);
}

// ---------------- smem layout ----------------
// A tile: 128 rows x 32 k halves (64B data), pitch 80B -> conflict-free ldmatrix
// B tile: 32 k-rows x 128 n halves (256B data), pitch 272B -> conflict-free ldmatrix.trans
constexpr int A_PITCH = 80;
constexpr int A_ST = 128 * A_PITCH;            // 10240
constexpr int B_PITCH = 272;
constexpr int B_ST = 32 * B_PITCH;             // 8704
constexpr int SM_B_OFF = 3 * A_ST;             // 30720
constexpr int SMEM_TOT = SM_B_OFF + 3 * B_ST;  // 56832  (both GEMMs)

// ---------------- 0) fp32 -> fp16 weight prepass ----------------
__global__ __launch_bounds__(256) void to_half_kernel(const float4* __restrict__ src,
                                                      uint4* __restrict__ dst, int n8) {
    int i = blockIdx.x * 256 + threadIdx.x;
    if (i >= n8) return;
    float4 a = src[2 * i], b = src[2 * i + 1];
    uint4 o;
    o.x = packh2(a.x, a.y);
    o.y = packh2(a.z, a.w);
    o.z = packh2(b.x, b.y);
    o.w = packh2(b.z, b.w);
    dst[i] = o;
}

// ---------------- 1) router ----------------
__global__ __launch_bounds__(256) void router_kernel(const float* __restrict__ x,
                                                     const float* __restrict__ Wg) {
    int warp = threadIdx.x >> 5, lane = threadIdx.x & 31;
    int token = blockIdx.x * 8 + warp;
    if (token >= Nn) return;
    const float* xr = x + (size_t)token * Dd;
    float acc[Ee];
#pragma unroll
    for (int e = 0; e < Ee; e++) acc[e] = 0.f;
    for (int k = lane; k < Dd; k += 32) {
        float xv = xr[k];
#pragma unroll
        for (int e = 0; e < Ee; e++) acc[e] += xv * Wg[e * Dd + k];
    }
#pragma unroll
    for (int e = 0; e < Ee; e++)
#pragma unroll
        for (int off = 16; off > 0; off >>= 1)
            acc[e] += __shfl_xor_sync(0xffffffffu, acc[e], off);
    if (lane == 0) {
        float v0 = -1e30f; int e0 = 0;
#pragma unroll
        for (int e = 0; e < Ee; e++) if (acc[e] > v0) { v0 = acc[e]; e0 = e; }
        float v1 = -1e30f; int e1 = 0;
#pragma unroll
        for (int e = 0; e < Ee; e++) if (e != e0 && acc[e] > v1) { v1 = acc[e]; e1 = e; }
        float t = expf(v1 - v0);
        int s = token * 2;
        g_slot_e[s] = e0; g_slot_e[s + 1] = e1;
        g_slot_gate[s]     = 1.0f / (1.0f + t);
        g_slot_gate[s + 1] = t / (1.0f + t);
    }
}

// ---------------- 2) capacity scan (shuffle-based, 2 syncthreads) ----------------
__global__ __launch_bounds__(1024) void scan_kernel() {
    __shared__ uint32_t wsum[32][4];
    int t = threadIdx.x;
    int lane = t & 31, warp = t >> 5;

    int se[8];
    uint32_t pk[4] = {0u, 0u, 0u, 0u};
    int base = t * 8;
#pragma unroll
    for (int i = 0; i < 8; i++) {
        se[i] = g_slot_e[base + i];
        pk[se[i] >> 1] += 1u << ((se[i] & 1) * 16);
    }

    uint32_t inc[4];
#pragma unroll
    for (int j = 0; j < 4; j++) inc[j] = pk[j];
#pragma unroll
    for (int off = 1; off < 32; off <<= 1) {
#pragma unroll
        for (int j = 0; j < 4; j++) {
            uint32_t v = __shfl_up_sync(0xffffffffu, inc[j], off);
            if (lane >= off) inc[j] += v;
        }
    }
    if (lane == 31)
#pragma unroll
        for (int j = 0; j < 4; j++) wsum[warp][j] = inc[j];
    __syncthreads();

    if (warp == 0) {
        uint32_t w[4];
#pragma unroll
        for (int j = 0; j < 4; j++) w[j] = wsum[lane][j];
#pragma unroll
        for (int off = 1; off < 32; off <<= 1) {
#pragma unroll
            for (int j = 0; j < 4; j++) {
                uint32_t v = __shfl_up_sync(0xffffffffu, w[j], off);
                if (lane >= off) w[j] += v;
            }
        }
#pragma unroll
        for (int j = 0; j < 4; j++) wsum[lane][j] = w[j];
        if (lane == 31) {
#pragma unroll
            for (int j = 0; j < 4; j++) {
                int c0 = (int)(w[j] & 0xFFFFu), c1 = (int)(w[j] >> 16);
                g_count[2 * j]     = (c0 < CAP) ? c0 : CAP;
                g_count[2 * j + 1] = (c1 < CAP) ? c1 : CAP;
            }
        }
    }
    __syncthreads();

    int run[Ee];
#pragma unroll
    for (int j = 0; j < 4; j++) {
        uint32_t wp = (warp > 0) ? wsum[warp - 1][j] : 0u;
        uint32_t ex = wp + inc[j] - pk[j];
        run[2 * j]     = (int)(ex & 0xFFFFu);
        run[2 * j + 1] = (int)(ex >> 16);
    }
#pragma unroll
    for (int i = 0; i < 8; i++) {
        int e = se[i];
        int p = 0;
#pragma unroll
        for (int j = 0; j < Ee; j++)
            if (e == j) { p = run[j]; run[j] = p + 1; }
        g_slot_pos[base + i] = (p < CAP) ? p : -1;
    }
}

// ---------------- 3) gather -> fp16 ----------------
__global__ __launch_bounds__(256) void gather_kernel(const float* __restrict__ x) {
    int s = blockIdx.x;
    int p = g_slot_pos[s];
    if (p < 0) return;
    int e = g_slot_e[s];
    int token = s >> 1;
    float4 v = ((const float4*)(x + (size_t)token * Dd))[threadIdx.x];
    uint2 u;
    u.x = packh2(v.x, v.y);
    u.y = packh2(v.z, v.w);
    *(uint2*)(g_Xe + ((size_t)e * CAP + p) * Dd + threadIdx.x * 4) = u;
}

// ---------------- 4) GEMM1 (fp16 mma, 128x128 tile, 2 CTAs/SM) + fused GLU ----------------
// Block: 128 rows x (64 inp + 64 gate cols, interleaved per warp), K = 1024, BK = 32.
// 4 warps (2m x 2n), warp tile 64x64 (32 inp + 32 gate n-halves).
// grid (Ii/64 = 32, CAP/128 = 10, Ee), 128 threads.
__global__ __launch_bounds__(128, 2) void gemm1_glu_kernel() {
    extern __shared__ __align__(16) char smem[];
    constexpr int NIT = Dd / 32;   // 32
    int e = blockIdx.z;
    int m0 = blockIdx.y * 128;
    if (m0 >= g_count[e]) return;
    int n0 = blockIdx.x * 64;

    int tid = threadIdx.x;
    int warp = tid >> 5, lane = tid & 31;
    int wm = warp & 1, wn = warp >> 1;        // 2m x 2n
    int lg = lane >> 2, lt = lane & 3;
    int r8 = lane & 7, grp = lane >> 3;

    const __half* Ae  = g_Xe + ((size_t)e * CAP + m0) * Dd;
    const __half* W1e = g_W1h + (size_t)e * Dd * TWOI;
    uint32_t sb = smem_u32(smem);

    float c[4][8][4];
#pragma unroll
    for (int mf = 0; mf < 4; mf++)
#pragma unroll
        for (int nf = 0; nf < 8; nf++)
#pragma unroll
            for (int q = 0; q < 4; q++) c[mf][nf][q] = 0.f;

    auto load_stage = [&](int s, int it) {
        int k0 = it * 32;
        uint32_t da = sb + s * A_ST;
#pragma unroll
        for (int q = 0; q < 4; q++) {
            int j = tid + q * 128;
            int row = j >> 2, seg = j & 3;
            cp16(da + (uint32_t)(row * A_PITCH + seg * 16),
                 Ae + (size_t)row * Dd + k0 + seg * 8);
        }
        uint32_t db = sb + SM_B_OFF + s * B_ST;
        // chunk cc (0..15): warp_n = cc>>3, inp cols if !(cc&4), else gate (+Ii)
#pragma unroll
        for (int q = 0; q < 4; q++) {
            int j = tid + q * 128;
            int r = j >> 4, cc = j & 15;
            const __half* src = W1e + (size_t)(k0 + r) * TWOI + n0
                              + (cc >> 3) * 32 + (cc & 3) * 8 + ((cc & 4) ? Ii : 0);
            cp16(db + (uint32_t)(r * B_PITCH + cc * 16), src);
        }
        CP_COMMIT();
    };

    auto compute_stage = [&](int s) {
        uint32_t sa = sb + s * A_ST;
        uint32_t sbB = sb + SM_B_OFF + s * B_ST;
#pragma unroll
        for (int ks = 0; ks < 2; ks++) {
            uint32_t a[4][4];
#pragma unroll
            for (int mf = 0; mf < 4; mf++) {
                uint32_t addr = sa
                    + (uint32_t)((wm * 64 + mf * 16 + (grp & 1) * 8 + r8) * A_PITCH
                                 + ks * 32 + (grp >> 1) * 16);
                ldsm_x4(a[mf][0], a[mf][1], a[mf][2], a[mf][3], addr);
            }
#pragma unroll
            for (int ch = 0; ch < 4; ch++) {
                uint32_t b0, b1, b2, b3;
                uint32_t addr = sbB
                    + (uint32_t)((ks * 16 + (grp & 1) * 8 + r8) * B_PITCH
                                 + wn * 128 + ch * 32 + (grp >> 1) * 16);
                ldsm_x4_t(b0, b1, b2, b3, addr);
                int nf0 = ch * 2, nf1 = ch * 2 + 1;
#pragma unroll
                for (int mf = 0; mf < 4; mf++) {
                    mma_f16(c[mf][nf0][0], c[mf][nf0][1], c[mf][nf0][2], c[mf][nf0][3],
                            a[mf][0], a[mf][1], a[mf][2], a[mf][3], b0, b1);
                    mma_f16(c[mf][nf1][0], c[mf][nf1][1], c[mf][nf1][2], c[mf][nf1][3],
                            a[mf][0], a[mf][1], a[mf][2], a[mf][3], b2, b3);
                }
            }
        }
    };

    load_stage(0, 0);
    load_stage(1, 1);
    for (int it = 0; it < NIT; it++) {
        int s = it % 3;
        if (it < NIT - 1) { CP_WAIT1(); } else { CP_WAIT0(); }
        __syncthreads();
        if (it + 2 < NIT) load_stage((it + 2) % 3, it + 2);
        compute_stage(s);
    }

    // fused GLU epilogue: nf 0..3 = inp (warp halves 0..31), nf+4 = gate, same cols
#pragma unroll
    for (int mf = 0; mf < 4; mf++) {
#pragma unroll
        for (int nf = 0; nf < 4; nf++) {
            int row0 = m0 + wm * 64 + mf * 16 + lg;
            int col  = n0 + wn * 32 + nf * 8 + lt * 2;
            float* i4 = c[mf][nf];
            float* g4 = c[mf][nf + 4];
            uint32_t h01 = packh2(gelu(i4[0]) * g4[0], gelu(i4[1]) * g4[1]);
            uint32_t h23 = packh2(gelu(i4[2]) * g4[2], gelu(i4[3]) * g4[3]);
            *(uint32_t*)(g_Hg + ((size_t)e * CAP + row0) * Ii + col)      = h01;
            *(uint32_t*)(g_Hg + ((size_t)e * CAP + row0 + 8) * Ii + col) = h23;
        }
    }
}

// ---------------- 5) GEMM2: Oe = Hg @ W2 (fp16 mma, 128x128 tile, 2 CTAs/SM) ----------------
// 4 warps (2m x 2n), warp tile 64x64, K = 2048, BK = 32.
// grid (Dd/128 = 8, CAP/128 = 10, Ee), 128 threads.
__global__ __launch_bounds__(128, 2) void gemm2_kernel() {
    extern __shared__ __align__(16) char smem[];
    constexpr int NIT = Ii / 32;   // 64
    int e = blockIdx.z;
    int m0 = blockIdx.y * 128;
    if (m0 >= g_count[e]) return;
    int n0 = blockIdx.x * 128;

    int tid = threadIdx.x;
    int warp = tid >> 5, lane = tid & 31;
    int wm = warp & 1, wn = warp >> 1;
    int lg = lane >> 2, lt = lane & 3;
    int r8 = lane & 7, grp = lane >> 3;

    const __half* Ae  = g_Hg + ((size_t)e * CAP + m0) * Ii;
    const __half* W2e = g_W2h + (size_t)e * Ii * Dd;
    uint32_t sb = smem_u32(smem);

    float c[4][8][4];
#pragma unroll
    for (int mf = 0; mf < 4; mf++)
#pragma unroll
        for (int nf = 0; nf < 8; nf++)
#pragma unroll
            for (int q = 0; q < 4; q++) c[mf][nf][q] = 0.f;

    auto load_stage = [&](int s, int it) {
        int k0 = it * 32;
        uint32_t da = sb + s * A_ST;
#pragma unroll
        for (int q = 0; q < 4; q++) {
            int j = tid + q * 128;
            int row = j >> 2, seg = j & 3;
            cp16(da + (uint32_t)(row * A_PITCH + seg * 16),
                 Ae + (size_t)row * Ii + k0 + seg * 8);
        }
        uint32_t db = sb + SM_B_OFF + s * B_ST;
#pragma unroll
        for (int q = 0; q < 4; q++) {
            int j = tid + q * 128;
            int r = j >> 4, cc = j & 15;
            cp16(db + (uint32_t)(r * B_PITCH + cc * 16),
                 W2e + (size_t)(k0 + r) * Dd + n0 + cc * 8);
        }
        CP_COMMIT();
    };

    auto compute_stage = [&](int s) {
        uint32_t sa = sb + s * A_ST;
        uint32_t sbB = sb + SM_B_OFF + s * B_ST;
#pragma unroll
        for (int ks = 0; ks < 2; ks++) {
            uint32_t a[4][4];
#pragma unroll
            for (int mf = 0; mf < 4; mf++) {
                uint32_t addr = sa
                    + (uint32_t)((wm * 64 + mf * 16 + (grp & 1) * 8 + r8) * A_PITCH
                                 + ks * 32 + (grp >> 1) * 16);
                ldsm_x4(a[mf][0], a[mf][1], a[mf][2], a[mf][3], addr);
            }
#pragma unroll
            for (int ch = 0; ch < 4; ch++) {
                uint32_t b0, b1, b2, b3;
                uint32_t addr = sbB
                    + (uint32_t)((ks * 16 + (grp & 1) * 8 + r8) * B_PITCH
                                 + wn * 128 + ch * 32 + (grp >> 1) * 16);
                ldsm_x4_t(b0, b1, b2, b3, addr);
                int nf0 = ch * 2, nf1 = ch * 2 + 1;
#pragma unroll
                for (int mf = 0; mf < 4; mf++) {
                    mma_f16(c[mf][nf0][0], c[mf][nf0][1], c[mf][nf0][2], c[mf][nf0][3],
                            a[mf][0], a[mf][1], a[mf][2], a[mf][3], b0, b1);
                    mma_f16(c[mf][nf1][0], c[mf][nf1][1], c[mf][nf1][2], c[mf][nf1][3],
                            a[mf][0], a[mf][1], a[mf][2], a[mf][3], b2, b3);
                }
            }
        }
    };

    load_stage(0, 0);
    load_stage(1, 1);
    for (int it = 0; it < NIT; it++) {
        int s = it % 3;
        if (it < NIT - 1) { CP_WAIT1(); } else { CP_WAIT0(); }
        __syncthreads();
        if (it + 2 < NIT) load_stage((it + 2) % 3, it + 2);
        compute_stage(s);
    }

#pragma unroll
    for (int mf = 0; mf < 4; mf++) {
#pragma unroll
        for (int nf = 0; nf < 8; nf++) {
            int row0 = m0 + wm * 64 + mf * 16 + lg;
            int col  = n0 + wn * 64 + nf * 8 + lt * 2;
            *(float2*)(g_Oe + ((size_t)e * CAP + row0) * Dd + col) =
                make_float2(c[mf][nf][0], c[mf][nf][1]);
            *(float2*)(g_Oe + ((size_t)e * CAP + row0 + 8) * Dd + col) =
                make_float2(c[mf][nf][2], c[mf][nf][3]);
        }
    }
}

// ---------------- 6) combine ----------------
__global__ __launch_bounds__(256) void combine_kernel(float* __restrict__ out) {
    int token = blockIdx.x;
    int s0 = token * 2, s1 = s0 + 1;
    int e0 = g_slot_e[s0], p0 = g_slot_pos[s0];
    int e1 = g_slot_e[s1], p1 = g_slot_pos[s1];
    float g0 = g_slot_gate[s0], g1 = g_slot_gate[s1];
    int i = threadIdx.x;
    float4 acc = make_float4(0.f, 0.f, 0.f, 0.f);
    if (p0 >= 0) {
        float4 v = *(const float4*)(g_Oe + ((size_t)e0 * CAP + p0) * Dd + i * 4);
        acc.x += g0 * v.x; acc.y += g0 * v.y; acc.z += g0 * v.z; acc.w += g0 * v.w;
    }
    if (p1 >= 0) {
        float4 v = *(const float4*)(g_Oe + ((size_t)e1 * CAP + p1) * Dd + i * 4);
        acc.x += g1 * v.x; acc.y += g1 * v.y; acc.z += g1 * v.z; acc.w += g1 * v.w;
    }
    *(float4*)(out + (size_t)token * Dd + i * 4) = acc;
}

// ---------------- launch (forked graph: prepass || routing chain) ----------------
extern "C" void kernel_launch(void* const* d_in, const int* in_sizes, int n_in,
                              void* d_out, int out_size) {
    const float* x  = (const float*)d_in[0];
    const float* Wg = (const float*)d_in[1];
    const float* W1 = (const float*)d_in[2];
    const float* W2 = (const float*)d_in[3];
    float* out = (float*)d_out;

    void *pW1h, *pW2h;
    cudaGetSymbolAddress(&pW1h, g_W1h);
    cudaGetSymbolAddress(&pW2h, g_W2h);

    // one-time resources (host-side only; no device allocation)
    static cudaStream_t s1 = nullptr, s2 = nullptr;
    static cudaEvent_t evRoot = nullptr, evW1 = nullptr, evW2 = nullptr;
    if (s1 == nullptr) {
        cudaStreamCreateWithFlags(&s1, cudaStreamNonBlocking);
        cudaStreamCreateWithFlags(&s2, cudaStreamNonBlocking);
        cudaEventCreateWithFlags(&evRoot, cudaEventDisableTiming);
        cudaEventCreateWithFlags(&evW1,   cudaEventDisableTiming);
        cudaEventCreateWithFlags(&evW2,   cudaEventDisableTiming);
        cudaFuncSetAttribute(gemm1_glu_kernel,
                             cudaFuncAttributeMaxDynamicSharedMemorySize, SMEM_TOT);
        cudaFuncSetAttribute(gemm2_kernel,
                             cudaFuncAttributeMaxDynamicSharedMemorySize, SMEM_TOT);
    }

    // fork: weight prepasses run parallel to the routing chain
    cudaEventRecord(evRoot, 0);
    cudaStreamWaitEvent(s1, evRoot, 0);
    cudaStreamWaitEvent(s2, evRoot, 0);

    {
        int n8_1 = (int)((size_t)Ee * Dd * TWOI / 8);
        int n8_2 = (int)((size_t)Ee * Ii * Dd / 8);
        to_half_kernel<<<(n8_1 + 255) / 256, 256, 0, s1>>>((const float4*)W1, (uint4*)pW1h, n8_1);
        to_half_kernel<<<(n8_2 + 255) / 256, 256, 0, s2>>>((const float4*)W2, (uint4*)pW2h, n8_2);
    }

    router_kernel<<<Nn / 8, 256>>>(x, Wg);
    scan_kernel<<<1, 1024>>>();
    gather_kernel<<<NS, 256>>>(x);

    // join W1 prepass before GEMM1
    cudaEventRecord(evW1, s1);
    cudaStreamWaitEvent(0, evW1, 0);
    gemm1_glu_kernel<<<dim3(Ii / 64, CAP / 128, Ee), 128, SMEM_TOT>>>();

    // join W2 prepass before GEMM2 (overlaps GEMM1)
    cudaEventRecord(evW2, s2);
    cudaStreamWaitEvent(0, evW2, 0);
    gemm2_kernel<<<dim3(Dd / 128, CAP / 128, Ee), 128, SMEM_TOT>>>();

    combine_kernel<<<Nn, 256>>>(out);
}